// round 12
// baseline (speedup 1.0000x reference)
#include <cuda_runtime.h>
#include <cuda_bf16.h>
#include <math.h>

#define NN 50000
#define NE 800000
#define D  64
#define NG 128
#define DH 32
#define NC 6

// ---------------- scratch (device globals; no allocation allowed) ----------
__device__ float g_h[NN * D];       // hidden state
__device__ float g_m[NN * D];       // per-node messages m = h @ W[l]
__device__ float g_agg[NN * D];     // scatter-add destination
__device__ float g_pooled[NG * D];  // graph pooling sums

__device__ __forceinline__ float sigf(float x) {
    return __fdividef(1.f, 1.f + __expf(-x));
}
__device__ __forceinline__ float tanhfast(float x) {
    return __fdividef(2.f, 1.f + __expf(-2.f * x)) - 1.f;
}

// bf16 split helpers: v = hi + lo with |residual| ~ 2^-16 |v|
__device__ __forceinline__ void split1(float v, __nv_bfloat16& h, __nv_bfloat16& l) {
    h = __float2bfloat16(v);
    l = __float2bfloat16(v - __bfloat162float(h));
}
__device__ __forceinline__ void split_pair(float v0, float v1, unsigned& hi, unsigned& lo) {
    __nv_bfloat16 h0, l0, h1, l1;
    split1(v0, h0, l0);
    split1(v1, h1, l1);
    hi = (unsigned)__bfloat16_as_ushort(h0) | ((unsigned)__bfloat16_as_ushort(h1) << 16);
    lo = (unsigned)__bfloat16_as_ushort(l0) | ((unsigned)__bfloat16_as_ushort(l1) << 16);
}
// vector split: float2 -> (bf16x2 hi word, bf16x2 lo word)
__device__ __forceinline__ void split2v(float2 v, unsigned& hi, unsigned& lo) {
    __nv_bfloat162 h = __float22bfloat162_rn(v);
    float2 r = __bfloat1622float2(h);
    __nv_bfloat162 l = __float22bfloat162_rn(make_float2(v.x - r.x, v.y - r.y));
    hi = *(unsigned*)&h;
    lo = *(unsigned*)&l;
}

// mma.sync m16n8k16 bf16 -> f32 accumulate
__device__ __forceinline__ void mma16816(float* c, const unsigned* a, const unsigned* b) {
    asm volatile(
        "mma.sync.aligned.m16n8k16.row.col.f32.bf16.bf16.f32 "
        "{%0,%1,%2,%3}, {%4,%5,%6,%7}, {%8,%9}, {%0,%1,%2,%3};"
        : "+f"(c[0]), "+f"(c[1]), "+f"(c[2]), "+f"(c[3])
        : "r"(a[0]), "r"(a[1]), "r"(a[2]), "r"(a[3]), "r"(b[0]), "r"(b[1]));
}

// ---------------- init: zero pooled sums ------------------------------------
__global__ void k_init() {
    int i = blockIdx.x * 256 + threadIdx.x;
    if (i < NG * D) g_pooled[i] = 0.f;
}

// ---------------- m = h @ W[layer] via bf16x3 tensor cores; zeroes agg ------
// Double-buffered pipeline (unchanged from measured-good R10 version).
__global__ __launch_bounds__(256, 1)
void k_mgemm(const float* __restrict__ x, const float* __restrict__ W, int layer) {
    __shared__ __align__(16) __nv_bfloat16 s_hhi[2][16 * 72];
    __shared__ __align__(16) __nv_bfloat16 s_hlo[2][16 * 72];

    int tid = threadIdx.x;
    int wid = tid >> 5, lane = tid & 31;
    int tg = lane & 3, gid = lane >> 2;
    int dbase = wid * 8;
    int d0 = dbase + tg * 2;

    const float* Wl = W + layer * 64 * 64;
    unsigned Bhi[4][2], Blo[4][2];
#pragma unroll
    for (int kt = 0; kt < 4; kt++) {
        int k0 = kt * 16 + tg * 2;
        int nc = dbase + gid;
        split_pair(Wl[(k0)     * 64 + nc], Wl[(k0 + 1) * 64 + nc], Bhi[kt][0], Blo[kt][0]);
        split_pair(Wl[(k0 + 8) * 64 + nc], Wl[(k0 + 9) * 64 + nc], Bhi[kt][1], Blo[kt][1]);
    }

    const float* hin = layer ? g_h : x;
    int srow = tid >> 4;
    int scol = (tid & 15) * 4;
    const int stride = gridDim.x * 16;

    int chunk = blockIdx.x * 16;
    float4 vh;
    if (chunk < NN) {
        vh = *(const float4*)&hin[chunk * 64 + srow * 64 + scol];
        unsigned h01, l01, h23, l23;
        split2v(make_float2(vh.x, vh.y), h01, l01);
        split2v(make_float2(vh.z, vh.w), h23, l23);
        *(uint2*)&s_hhi[0][srow * 72 + scol] = make_uint2(h01, h23);
        *(uint2*)&s_hlo[0][srow * 72 + scol] = make_uint2(l01, l23);
    }
    __syncthreads();

    for (int it = 0; chunk < NN; chunk += stride, it++) {
        int buf = it & 1;
        int next = chunk + stride;
        if (next < NN)
            vh = *(const float4*)&hin[next * 64 + srow * 64 + scol];

        float C[4] = {0.f, 0.f, 0.f, 0.f};
#pragma unroll
        for (int kt = 0; kt < 4; kt++) {
            int k0 = kt * 16 + tg * 2;
            unsigned ahi[4], alo[4];
            ahi[0] = *(const unsigned*)&s_hhi[buf][(gid)     * 72 + k0];
            ahi[1] = *(const unsigned*)&s_hhi[buf][(gid + 8) * 72 + k0];
            ahi[2] = *(const unsigned*)&s_hhi[buf][(gid)     * 72 + k0 + 8];
            ahi[3] = *(const unsigned*)&s_hhi[buf][(gid + 8) * 72 + k0 + 8];
            alo[0] = *(const unsigned*)&s_hlo[buf][(gid)     * 72 + k0];
            alo[1] = *(const unsigned*)&s_hlo[buf][(gid + 8) * 72 + k0];
            alo[2] = *(const unsigned*)&s_hlo[buf][(gid)     * 72 + k0 + 8];
            alo[3] = *(const unsigned*)&s_hlo[buf][(gid + 8) * 72 + k0 + 8];
            mma16816(C, ahi, Bhi[kt]);
            mma16816(C, ahi, Blo[kt]);
            mma16816(C, alo, Bhi[kt]);
        }

#pragma unroll
        for (int p = 0; p < 2; p++) {
            int node = chunk + gid + p * 8;
            *(float2*)&g_m[node * 64 + d0] = make_float2(C[p * 2], C[p * 2 + 1]);
            *(float2*)&g_agg[node * 64 + d0] = make_float2(0.f, 0.f);
        }

        if (next < NN) {
            unsigned h01, l01, h23, l23;
            split2v(make_float2(vh.x, vh.y), h01, l01);
            split2v(make_float2(vh.z, vh.w), h23, l23);
            *(uint2*)&s_hhi[buf ^ 1][srow * 72 + scol] = make_uint2(h01, h23);
            *(uint2*)&s_hlo[buf ^ 1][srow * 72 + scol] = make_uint2(l01, l23);
        }
        __syncthreads();
    }
}

// ---------------- edge scatter: agg[dst] += m[src] --------------------------
// Grid-stride persistent form: 1250 blocks x 256 threads, each thread walks
// exactly 40 (edge, quad) items; unroll-4 gives independent index->gather->RED
// chains (MLP>=4) and removes 48k block launch/drain transitions.
#define SC_BLOCKS 1250
#define SC_ITERS  40   // NE*16 / (SC_BLOCKS*256)

__global__ void k_scatter(const int* __restrict__ ei) {
    int t0 = blockIdx.x * 256 + threadIdx.x;
    const int NT = SC_BLOCKS * 256;
#pragma unroll 4
    for (int i = 0; i < SC_ITERS; i++) {
        int t = t0 + i * NT;
        int e = t >> 4;
        int q = t & 15;
        int src = __ldg(&ei[e]);
        int dst = __ldg(&ei[NE + e]);
        float4 v = *reinterpret_cast<const float4*>(&g_m[src * 64 + q * 4]);
        atomicAdd(reinterpret_cast<float4*>(&g_agg[dst * 64 + q * 4]), v);
    }
}

// ---------------- fused GRU gates, 16-warp split, 32-node M-tile ------------
// Warps 0-7: agg-side gates with w_ih; warps 8-15: h-side gates with w_hh.
// Each warp owns 2 row-blocks (rows 0-15, 16-31) -> 6 independent MMA chains.
// C fragments exchanged via smem sC; epilogue threads own 2 rows x 2 cols.
#define MT 32
#define GATES_SMEM (4 * (2 * MT * 72) * 2 + 2 * MT * 68 * 4 + 6 * MT * 72 * 4)

__global__ __launch_bounds__(512, 1)
void k_gates(const float* __restrict__ x,
             const float* __restrict__ w_ih, const float* __restrict__ w_hh,
             const float* __restrict__ b_ih, const float* __restrict__ b_hh,
             const int* __restrict__ batch, int layer) {
    extern __shared__ __align__(16) char smraw[];
    __nv_bfloat16* s_ahi = (__nv_bfloat16*)smraw;      // [2][MT*72]
    __nv_bfloat16* s_alo = s_ahi + 2 * MT * 72;
    __nv_bfloat16* s_hhi = s_alo + 2 * MT * 72;
    __nv_bfloat16* s_hlo = s_hhi + 2 * MT * 72;
    float* s_hf = (float*)(s_hlo + 2 * MT * 72);       // [2][MT*68]
    float* sC   = s_hf + 2 * MT * 68;                  // [6][MT*72]

    int tid = threadIdx.x;
    int wid = tid >> 5, lane = tid & 31;
    int side = wid >> 3, w8 = wid & 7;
    int tg = lane & 3, gid = lane >> 2;
    int d0 = w8 * 8 + tg * 2;

    // B fragments: this warp's side only (3 gates) -> 48 regs.
    const float* wm = side ? w_hh : w_ih;
    unsigned Bhi[3][4][2], Blo[3][4][2];
#pragma unroll
    for (int g = 0; g < 3; g++) {
        const float* wr = wm + (g * 64 + w8 * 8 + gid) * 64;
#pragma unroll
        for (int kt = 0; kt < 4; kt++) {
            int k0 = kt * 16 + tg * 2;
            split_pair(wr[k0],     wr[k0 + 1], Bhi[g][kt][0], Blo[g][kt][0]);
            split_pair(wr[k0 + 8], wr[k0 + 9], Bhi[g][kt][1], Blo[g][kt][1]);
        }
    }

    // staging coords: 512 threads cover MT rows x 16 float4/row
    int srow = tid >> 4;          // 0..31
    int scol = (tid & 15) * 4;
    // epilogue coords: rows erow, erow+16; cols ecol..ecol+1
    int erow = tid >> 5;          // 0..15
    int ecol = lane * 2;
    float2 ebi0 = *(const float2*)&b_ih[ecol];
    float2 ebi1 = *(const float2*)&b_ih[64 + ecol];
    float2 ebi2 = *(const float2*)&b_ih[128 + ecol];
    float2 ebh0 = *(const float2*)&b_hh[ecol];
    float2 ebh1 = *(const float2*)&b_hh[64 + ecol];
    float2 ebh2 = *(const float2*)&b_hh[128 + ecol];

    const float* hin = layer ? g_h : x;
    const __nv_bfloat16* pAhi = side ? s_hhi : s_ahi;
    const __nv_bfloat16* pAlo = side ? s_hlo : s_alo;
    const int stride = gridDim.x * MT;

    int chunk = blockIdx.x * MT;
    float4 va, vh;
    if (chunk + srow < NN) {
        va = *(const float4*)&g_agg[(chunk + srow) * 64 + scol];
        vh = *(const float4*)&hin[(chunk + srow) * 64 + scol];
        unsigned h01, l01, h23, l23;
        split2v(make_float2(va.x, va.y), h01, l01);
        split2v(make_float2(va.z, va.w), h23, l23);
        *(uint2*)&s_ahi[srow * 72 + scol] = make_uint2(h01, h23);
        *(uint2*)&s_alo[srow * 72 + scol] = make_uint2(l01, l23);
        split2v(make_float2(vh.x, vh.y), h01, l01);
        split2v(make_float2(vh.z, vh.w), h23, l23);
        *(uint2*)&s_hhi[srow * 72 + scol] = make_uint2(h01, h23);
        *(uint2*)&s_hlo[srow * 72 + scol] = make_uint2(l01, l23);
        *(float4*)&s_hf[srow * 68 + scol] = vh;
    }
    __syncthreads();

    for (int it = 0; chunk < NN; chunk += stride, it++) {
        int buf = it & 1;
        int abase = buf * MT * 72;
        int next = chunk + stride;
        if (next + srow < NN) {
            va = *(const float4*)&g_agg[(next + srow) * 64 + scol];
            vh = *(const float4*)&hin[(next + srow) * 64 + scol];
        }

        float C[3][2][4];
#pragma unroll
        for (int g = 0; g < 3; g++)
#pragma unroll
            for (int rb = 0; rb < 2; rb++)
#pragma unroll
                for (int q = 0; q < 4; q++) C[g][rb][q] = 0.f;

#pragma unroll
        for (int kt = 0; kt < 4; kt++) {
            int k0 = kt * 16 + tg * 2;
#pragma unroll
            for (int rb = 0; rb < 2; rb++) {
                int r0 = rb * 16 + gid;
                unsigned ahi[4], alo[4];
                ahi[0] = *(const unsigned*)&pAhi[abase + (r0)     * 72 + k0];
                ahi[1] = *(const unsigned*)&pAhi[abase + (r0 + 8) * 72 + k0];
                ahi[2] = *(const unsigned*)&pAhi[abase + (r0)     * 72 + k0 + 8];
                ahi[3] = *(const unsigned*)&pAhi[abase + (r0 + 8) * 72 + k0 + 8];
                alo[0] = *(const unsigned*)&pAlo[abase + (r0)     * 72 + k0];
                alo[1] = *(const unsigned*)&pAlo[abase + (r0 + 8) * 72 + k0];
                alo[2] = *(const unsigned*)&pAlo[abase + (r0)     * 72 + k0 + 8];
                alo[3] = *(const unsigned*)&pAlo[abase + (r0 + 8) * 72 + k0 + 8];
#pragma unroll
                for (int g = 0; g < 3; g++) {
                    mma16816(C[g][rb], ahi, Bhi[g][kt]);
                    mma16816(C[g][rb], ahi, Blo[g][kt]);
                    mma16816(C[g][rb], alo, Bhi[g][kt]);
                }
            }
        }

        // publish C fragments to smem
#pragma unroll
        for (int g = 0; g < 3; g++)
#pragma unroll
            for (int rb = 0; rb < 2; rb++)
#pragma unroll
                for (int p = 0; p < 2; p++)
                    *(float2*)&sC[((side * 3 + g) * MT + rb * 16 + gid + p * 8) * 72 + d0] =
                        make_float2(C[g][rb][2 * p], C[g][rb][2 * p + 1]);
        __syncthreads();

        // epilogue: each thread owns 2 rows (erow, erow+16) x 2 cols
#pragma unroll
        for (int rr = 0; rr < 2; rr++) {
            int row = erow + rr * 16;
            int node = chunk + row;
            if (node < NN) {
                float2 ir = *(float2*)&sC[(0 * MT + row) * 72 + ecol];
                float2 iz = *(float2*)&sC[(1 * MT + row) * 72 + ecol];
                float2 ix = *(float2*)&sC[(2 * MT + row) * 72 + ecol];
                float2 hr = *(float2*)&sC[(3 * MT + row) * 72 + ecol];
                float2 hz = *(float2*)&sC[(4 * MT + row) * 72 + ecol];
                float2 hn = *(float2*)&sC[(5 * MT + row) * 72 + ecol];
                float2 ho = *(float2*)&s_hf[buf * MT * 68 + row * 68 + ecol];

                float r0 = sigf(ir.x + ebi0.x + hr.x + ebh0.x);
                float z0 = sigf(iz.x + ebi1.x + hz.x + ebh1.x);
                float n0 = tanhfast(ix.x + ebi2.x + r0 * (hn.x + ebh2.x));
                float h0 = (1.f - z0) * n0 + z0 * ho.x;
                float r1 = sigf(ir.y + ebi0.y + hr.y + ebh0.y);
                float z1 = sigf(iz.y + ebi1.y + hz.y + ebh1.y);
                float n1 = tanhfast(ix.y + ebi2.y + r1 * (hn.y + ebh2.y));
                float h1 = (1.f - z1) * n1 + z1 * ho.y;

                if (layer == 0) {
                    *(float2*)&g_h[node * 64 + ecol] = make_float2(h0, h1);
                } else {
                    float2 rv = make_float2(fmaxf(h0, 0.f), fmaxf(h1, 0.f));
                    atomicAdd((float2*)&g_pooled[batch[node] * 64 + ecol], rv);
                }
            }
        }

        // stage next chunk into the other buffer
        if (next + srow < NN) {
            unsigned h01, l01;
            split2v(make_float2(va.x, va.y), h01, l01);
            unsigned h23, l23;
            split2v(make_float2(va.z, va.w), h23, l23);
            *(uint2*)&s_ahi[(buf ^ 1) * MT * 72 + srow * 72 + scol] = make_uint2(h01, h23);
            *(uint2*)&s_alo[(buf ^ 1) * MT * 72 + srow * 72 + scol] = make_uint2(l01, l23);
            split2v(make_float2(vh.x, vh.y), h01, l01);
            split2v(make_float2(vh.z, vh.w), h23, l23);
            *(uint2*)&s_hhi[(buf ^ 1) * MT * 72 + srow * 72 + scol] = make_uint2(h01, h23);
            *(uint2*)&s_hlo[(buf ^ 1) * MT * 72 + srow * 72 + scol] = make_uint2(l01, l23);
            *(float4*)&s_hf[(buf ^ 1) * MT * 68 + srow * 68 + scol] = vh;
        }
        __syncthreads();
    }
}

// ---------------- mean pool + fc1(relu) + fc2 + log_softmax -----------------
__device__ __forceinline__ int lbound(const int* __restrict__ b, int v) {
    int lo = 0, hi = NN;
    while (lo < hi) {
        int m = (lo + hi) >> 1;
        if (b[m] < v) lo = m + 1; else hi = m;
    }
    return lo;
}

__global__ void k_poolfc(const int* __restrict__ batch,
                         const float* __restrict__ fc1w, const float* __restrict__ fc1b,
                         const float* __restrict__ fc2w, const float* __restrict__ fc2b,
                         float* __restrict__ out) {
    int g = threadIdx.x;
    if (g >= NG) return;
    int cnt = lbound(batch, g + 1) - lbound(batch, g);
    float inv = 1.f / fmaxf((float)cnt, 1.f);
    float p[D];
#pragma unroll
    for (int k = 0; k < D; k++) p[k] = g_pooled[g * D + k] * inv;

    float y[DH];
#pragma unroll
    for (int j = 0; j < DH; j++) {
        float s = fc1b[j];
#pragma unroll
        for (int k = 0; k < D; k++) s += p[k] * fc1w[j * D + k];
        y[j] = fmaxf(s, 0.f);
    }

    float z[NC];
    float mx = -1e30f;
#pragma unroll
    for (int c = 0; c < NC; c++) {
        float s = fc2b[c];
#pragma unroll
        for (int j = 0; j < DH; j++) s += y[j] * fc2w[c * DH + j];
        z[c] = s;
        mx = fmaxf(mx, s);
    }
    float lse = 0.f;
#pragma unroll
    for (int c = 0; c < NC; c++) lse += expf(z[c] - mx);
    lse = logf(lse) + mx;
#pragma unroll
    for (int c = 0; c < NC; c++) out[g * NC + c] = z[c] - lse;
}

// ---------------- launch -----------------------------------------------------
extern "C" void kernel_launch(void* const* d_in, const int* in_sizes, int n_in,
                              void* d_out, int out_size) {
    const float* x     = (const float*)d_in[0];
    const int*   ei    = (const int*)d_in[1];
    const int*   batch = (const int*)d_in[2];
    const float* W     = (const float*)d_in[3];
    const float* w_ih  = (const float*)d_in[4];
    const float* w_hh  = (const float*)d_in[5];
    const float* b_ih  = (const float*)d_in[6];
    const float* b_hh  = (const float*)d_in[7];
    const float* fc1w  = (const float*)d_in[8];
    const float* fc1b  = (const float*)d_in[9];
    const float* fc2w  = (const float*)d_in[10];
    const float* fc2b  = (const float*)d_in[11];
    float* out = (float*)d_out;

    cudaFuncSetAttribute(k_gates, cudaFuncAttributeMaxDynamicSharedMemorySize,
                         GATES_SMEM);

    k_init<<<32, 256>>>();

    for (int l = 0; l < 2; l++) {
        k_mgemm<<<592, 256>>>(x, W, l);
        k_scatter<<<SC_BLOCKS, 256>>>(ei);
        k_gates<<<148, 512, GATES_SMEM>>>(x, w_ih, w_hh, b_ih, b_hh, batch, l);
    }
    k_poolfc<<<1, 128>>>(batch, fc1w, fc1b, fc2w, fc2b, out);
}

// round 13
// speedup vs baseline: 1.0893x; 1.0893x over previous
#include <cuda_runtime.h>
#include <cuda_bf16.h>
#include <math.h>

#define NN 50000
#define NE 800000
#define D  64
#define NG 128
#define DH 32
#define NC 6

// ---------------- scratch (device globals; no allocation allowed) ----------
__device__ float g_h[NN * D];       // hidden state
__device__ float g_m[NN * D];       // per-node messages m = h @ W[l]
__device__ float g_agg[NN * D];     // scatter-add destination
__device__ float g_pooled[NG * D];  // graph pooling sums

__device__ __forceinline__ float sigf(float x) {
    return __fdividef(1.f, 1.f + __expf(-x));
}
__device__ __forceinline__ float tanhfast(float x) {
    return __fdividef(2.f, 1.f + __expf(-2.f * x)) - 1.f;
}

// bf16 split helpers: v = hi + lo with |residual| ~ 2^-16 |v|
__device__ __forceinline__ void split1(float v, __nv_bfloat16& h, __nv_bfloat16& l) {
    h = __float2bfloat16(v);
    l = __float2bfloat16(v - __bfloat162float(h));
}
__device__ __forceinline__ void split_pair(float v0, float v1, unsigned& hi, unsigned& lo) {
    __nv_bfloat16 h0, l0, h1, l1;
    split1(v0, h0, l0);
    split1(v1, h1, l1);
    hi = (unsigned)__bfloat16_as_ushort(h0) | ((unsigned)__bfloat16_as_ushort(h1) << 16);
    lo = (unsigned)__bfloat16_as_ushort(l0) | ((unsigned)__bfloat16_as_ushort(l1) << 16);
}
// vector split: float2 -> (bf16x2 hi word, bf16x2 lo word)
__device__ __forceinline__ void split2v(float2 v, unsigned& hi, unsigned& lo) {
    __nv_bfloat162 h = __float22bfloat162_rn(v);
    float2 r = __bfloat1622float2(h);
    __nv_bfloat162 l = __float22bfloat162_rn(make_float2(v.x - r.x, v.y - r.y));
    hi = *(unsigned*)&h;
    lo = *(unsigned*)&l;
}

// mma.sync m16n8k16 bf16 -> f32 accumulate
__device__ __forceinline__ void mma16816(float* c, const unsigned* a, const unsigned* b) {
    asm volatile(
        "mma.sync.aligned.m16n8k16.row.col.f32.bf16.bf16.f32 "
        "{%0,%1,%2,%3}, {%4,%5,%6,%7}, {%8,%9}, {%0,%1,%2,%3};"
        : "+f"(c[0]), "+f"(c[1]), "+f"(c[2]), "+f"(c[3])
        : "r"(a[0]), "r"(a[1]), "r"(a[2]), "r"(a[3]), "r"(b[0]), "r"(b[1]));
}

// ---------------- init: zero pooled sums ------------------------------------
__global__ void k_init() {
    int i = blockIdx.x * 256 + threadIdx.x;
    if (i < NG * D) g_pooled[i] = 0.f;
}

// ---------------- m = h @ W[layer] via bf16x3 tensor cores; zeroes agg ------
// Double-buffered pipeline (unchanged from measured-good R10 version).
__global__ __launch_bounds__(256, 1)
void k_mgemm(const float* __restrict__ x, const float* __restrict__ W, int layer) {
    __shared__ __align__(16) __nv_bfloat16 s_hhi[2][16 * 72];
    __shared__ __align__(16) __nv_bfloat16 s_hlo[2][16 * 72];

    int tid = threadIdx.x;
    int wid = tid >> 5, lane = tid & 31;
    int tg = lane & 3, gid = lane >> 2;
    int dbase = wid * 8;
    int d0 = dbase + tg * 2;

    const float* Wl = W + layer * 64 * 64;
    unsigned Bhi[4][2], Blo[4][2];
#pragma unroll
    for (int kt = 0; kt < 4; kt++) {
        int k0 = kt * 16 + tg * 2;
        int nc = dbase + gid;
        split_pair(Wl[(k0)     * 64 + nc], Wl[(k0 + 1) * 64 + nc], Bhi[kt][0], Blo[kt][0]);
        split_pair(Wl[(k0 + 8) * 64 + nc], Wl[(k0 + 9) * 64 + nc], Bhi[kt][1], Blo[kt][1]);
    }

    const float* hin = layer ? g_h : x;
    int srow = tid >> 4;
    int scol = (tid & 15) * 4;
    const int stride = gridDim.x * 16;

    int chunk = blockIdx.x * 16;
    float4 vh;
    if (chunk < NN) {
        vh = *(const float4*)&hin[chunk * 64 + srow * 64 + scol];
        unsigned h01, l01, h23, l23;
        split2v(make_float2(vh.x, vh.y), h01, l01);
        split2v(make_float2(vh.z, vh.w), h23, l23);
        *(uint2*)&s_hhi[0][srow * 72 + scol] = make_uint2(h01, h23);
        *(uint2*)&s_hlo[0][srow * 72 + scol] = make_uint2(l01, l23);
    }
    __syncthreads();

    for (int it = 0; chunk < NN; chunk += stride, it++) {
        int buf = it & 1;
        int next = chunk + stride;
        if (next < NN)
            vh = *(const float4*)&hin[next * 64 + srow * 64 + scol];

        float C[4] = {0.f, 0.f, 0.f, 0.f};
#pragma unroll
        for (int kt = 0; kt < 4; kt++) {
            int k0 = kt * 16 + tg * 2;
            unsigned ahi[4], alo[4];
            ahi[0] = *(const unsigned*)&s_hhi[buf][(gid)     * 72 + k0];
            ahi[1] = *(const unsigned*)&s_hhi[buf][(gid + 8) * 72 + k0];
            ahi[2] = *(const unsigned*)&s_hhi[buf][(gid)     * 72 + k0 + 8];
            ahi[3] = *(const unsigned*)&s_hhi[buf][(gid + 8) * 72 + k0 + 8];
            alo[0] = *(const unsigned*)&s_hlo[buf][(gid)     * 72 + k0];
            alo[1] = *(const unsigned*)&s_hlo[buf][(gid + 8) * 72 + k0];
            alo[2] = *(const unsigned*)&s_hlo[buf][(gid)     * 72 + k0 + 8];
            alo[3] = *(const unsigned*)&s_hlo[buf][(gid + 8) * 72 + k0 + 8];
            mma16816(C, ahi, Bhi[kt]);
            mma16816(C, ahi, Blo[kt]);
            mma16816(C, alo, Bhi[kt]);
        }

#pragma unroll
        for (int p = 0; p < 2; p++) {
            int node = chunk + gid + p * 8;
            *(float2*)&g_m[node * 64 + d0] = make_float2(C[p * 2], C[p * 2 + 1]);
            *(float2*)&g_agg[node * 64 + d0] = make_float2(0.f, 0.f);
        }

        if (next < NN) {
            unsigned h01, l01, h23, l23;
            split2v(make_float2(vh.x, vh.y), h01, l01);
            split2v(make_float2(vh.z, vh.w), h23, l23);
            *(uint2*)&s_hhi[buf ^ 1][srow * 72 + scol] = make_uint2(h01, h23);
            *(uint2*)&s_hlo[buf ^ 1][srow * 72 + scol] = make_uint2(l01, l23);
        }
        __syncthreads();
    }
}

// ---------------- edge scatter: agg[dst] += m[src] --------------------------
// One thread per (4-edge group, 16B quad): int4 index loads amortize index
// traffic 4x; 4 independent gather->RED.128 chains per thread. Oversubscribed
// one-shot grid (12.5k blocks) -- the proven regime for this atomic stream.
__global__ void k_scatter(const int* __restrict__ ei) {
    int t = blockIdx.x * 256 + threadIdx.x;
    if (t >= NE * 4) return;
    int q = (t & 15) * 4;
    int eg = t >> 4;  // group of 4 consecutive edges
    int4 s4 = __ldg((const int4*)ei + eg);
    int4 d4 = __ldg((const int4*)(ei + NE) + eg);
    float4 v0 = *(const float4*)&g_m[s4.x * 64 + q];
    float4 v1 = *(const float4*)&g_m[s4.y * 64 + q];
    float4 v2 = *(const float4*)&g_m[s4.z * 64 + q];
    float4 v3 = *(const float4*)&g_m[s4.w * 64 + q];
    atomicAdd((float4*)&g_agg[d4.x * 64 + q], v0);
    atomicAdd((float4*)&g_agg[d4.y * 64 + q], v1);
    atomicAdd((float4*)&g_agg[d4.z * 64 + q], v2);
    atomicAdd((float4*)&g_agg[d4.w * 64 + q], v3);
}

// ---------------- fused GRU gates, 16-warp split, 32-node M-tile ------------
// (unchanged from R12 -- measured 31.8us)
#define MT 32
#define GATES_SMEM (4 * (2 * MT * 72) * 2 + 2 * MT * 68 * 4 + 6 * MT * 72 * 4)

__global__ __launch_bounds__(512, 1)
void k_gates(const float* __restrict__ x,
             const float* __restrict__ w_ih, const float* __restrict__ w_hh,
             const float* __restrict__ b_ih, const float* __restrict__ b_hh,
             const int* __restrict__ batch, int layer) {
    extern __shared__ __align__(16) char smraw[];
    __nv_bfloat16* s_ahi = (__nv_bfloat16*)smraw;      // [2][MT*72]
    __nv_bfloat16* s_alo = s_ahi + 2 * MT * 72;
    __nv_bfloat16* s_hhi = s_alo + 2 * MT * 72;
    __nv_bfloat16* s_hlo = s_hhi + 2 * MT * 72;
    float* s_hf = (float*)(s_hlo + 2 * MT * 72);       // [2][MT*68]
    float* sC   = s_hf + 2 * MT * 68;                  // [6][MT*72]

    int tid = threadIdx.x;
    int wid = tid >> 5, lane = tid & 31;
    int side = wid >> 3, w8 = wid & 7;
    int tg = lane & 3, gid = lane >> 2;
    int d0 = w8 * 8 + tg * 2;

    const float* wm = side ? w_hh : w_ih;
    unsigned Bhi[3][4][2], Blo[3][4][2];
#pragma unroll
    for (int g = 0; g < 3; g++) {
        const float* wr = wm + (g * 64 + w8 * 8 + gid) * 64;
#pragma unroll
        for (int kt = 0; kt < 4; kt++) {
            int k0 = kt * 16 + tg * 2;
            split_pair(wr[k0],     wr[k0 + 1], Bhi[g][kt][0], Blo[g][kt][0]);
            split_pair(wr[k0 + 8], wr[k0 + 9], Bhi[g][kt][1], Blo[g][kt][1]);
        }
    }

    int srow = tid >> 4;          // 0..31
    int scol = (tid & 15) * 4;
    int erow = tid >> 5;          // 0..15
    int ecol = lane * 2;
    float2 ebi0 = *(const float2*)&b_ih[ecol];
    float2 ebi1 = *(const float2*)&b_ih[64 + ecol];
    float2 ebi2 = *(const float2*)&b_ih[128 + ecol];
    float2 ebh0 = *(const float2*)&b_hh[ecol];
    float2 ebh1 = *(const float2*)&b_hh[64 + ecol];
    float2 ebh2 = *(const float2*)&b_hh[128 + ecol];

    const float* hin = layer ? g_h : x;
    const __nv_bfloat16* pAhi = side ? s_hhi : s_ahi;
    const __nv_bfloat16* pAlo = side ? s_hlo : s_alo;
    const int stride = gridDim.x * MT;

    int chunk = blockIdx.x * MT;
    float4 va, vh;
    if (chunk + srow < NN) {
        va = *(const float4*)&g_agg[(chunk + srow) * 64 + scol];
        vh = *(const float4*)&hin[(chunk + srow) * 64 + scol];
        unsigned h01, l01, h23, l23;
        split2v(make_float2(va.x, va.y), h01, l01);
        split2v(make_float2(va.z, va.w), h23, l23);
        *(uint2*)&s_ahi[srow * 72 + scol] = make_uint2(h01, h23);
        *(uint2*)&s_alo[srow * 72 + scol] = make_uint2(l01, l23);
        split2v(make_float2(vh.x, vh.y), h01, l01);
        split2v(make_float2(vh.z, vh.w), h23, l23);
        *(uint2*)&s_hhi[srow * 72 + scol] = make_uint2(h01, h23);
        *(uint2*)&s_hlo[srow * 72 + scol] = make_uint2(l01, l23);
        *(float4*)&s_hf[srow * 68 + scol] = vh;
    }
    __syncthreads();

    for (int it = 0; chunk < NN; chunk += stride, it++) {
        int buf = it & 1;
        int abase = buf * MT * 72;
        int next = chunk + stride;
        if (next + srow < NN) {
            va = *(const float4*)&g_agg[(next + srow) * 64 + scol];
            vh = *(const float4*)&hin[(next + srow) * 64 + scol];
        }

        float C[3][2][4];
#pragma unroll
        for (int g = 0; g < 3; g++)
#pragma unroll
            for (int rb = 0; rb < 2; rb++)
#pragma unroll
                for (int q = 0; q < 4; q++) C[g][rb][q] = 0.f;

#pragma unroll
        for (int kt = 0; kt < 4; kt++) {
            int k0 = kt * 16 + tg * 2;
#pragma unroll
            for (int rb = 0; rb < 2; rb++) {
                int r0 = rb * 16 + gid;
                unsigned ahi[4], alo[4];
                ahi[0] = *(const unsigned*)&pAhi[abase + (r0)     * 72 + k0];
                ahi[1] = *(const unsigned*)&pAhi[abase + (r0 + 8) * 72 + k0];
                ahi[2] = *(const unsigned*)&pAhi[abase + (r0)     * 72 + k0 + 8];
                ahi[3] = *(const unsigned*)&pAhi[abase + (r0 + 8) * 72 + k0 + 8];
                alo[0] = *(const unsigned*)&pAlo[abase + (r0)     * 72 + k0];
                alo[1] = *(const unsigned*)&pAlo[abase + (r0 + 8) * 72 + k0];
                alo[2] = *(const unsigned*)&pAlo[abase + (r0)     * 72 + k0 + 8];
                alo[3] = *(const unsigned*)&pAlo[abase + (r0 + 8) * 72 + k0 + 8];
#pragma unroll
                for (int g = 0; g < 3; g++) {
                    mma16816(C[g][rb], ahi, Bhi[g][kt]);
                    mma16816(C[g][rb], ahi, Blo[g][kt]);
                    mma16816(C[g][rb], alo, Bhi[g][kt]);
                }
            }
        }

#pragma unroll
        for (int g = 0; g < 3; g++)
#pragma unroll
            for (int rb = 0; rb < 2; rb++)
#pragma unroll
                for (int p = 0; p < 2; p++)
                    *(float2*)&sC[((side * 3 + g) * MT + rb * 16 + gid + p * 8) * 72 + d0] =
                        make_float2(C[g][rb][2 * p], C[g][rb][2 * p + 1]);
        __syncthreads();

#pragma unroll
        for (int rr = 0; rr < 2; rr++) {
            int row = erow + rr * 16;
            int node = chunk + row;
            if (node < NN) {
                float2 ir = *(float2*)&sC[(0 * MT + row) * 72 + ecol];
                float2 iz = *(float2*)&sC[(1 * MT + row) * 72 + ecol];
                float2 ix = *(float2*)&sC[(2 * MT + row) * 72 + ecol];
                float2 hr = *(float2*)&sC[(3 * MT + row) * 72 + ecol];
                float2 hz = *(float2*)&sC[(4 * MT + row) * 72 + ecol];
                float2 hn = *(float2*)&sC[(5 * MT + row) * 72 + ecol];
                float2 ho = *(float2*)&s_hf[buf * MT * 68 + row * 68 + ecol];

                float r0 = sigf(ir.x + ebi0.x + hr.x + ebh0.x);
                float z0 = sigf(iz.x + ebi1.x + hz.x + ebh1.x);
                float n0 = tanhfast(ix.x + ebi2.x + r0 * (hn.x + ebh2.x));
                float h0 = (1.f - z0) * n0 + z0 * ho.x;
                float r1 = sigf(ir.y + ebi0.y + hr.y + ebh0.y);
                float z1 = sigf(iz.y + ebi1.y + hz.y + ebh1.y);
                float n1 = tanhfast(ix.y + ebi2.y + r1 * (hn.y + ebh2.y));
                float h1 = (1.f - z1) * n1 + z1 * ho.y;

                if (layer == 0) {
                    *(float2*)&g_h[node * 64 + ecol] = make_float2(h0, h1);
                } else {
                    float2 rv = make_float2(fmaxf(h0, 0.f), fmaxf(h1, 0.f));
                    atomicAdd((float2*)&g_pooled[batch[node] * 64 + ecol], rv);
                }
            }
        }

        if (next + srow < NN) {
            unsigned h01, l01;
            split2v(make_float2(va.x, va.y), h01, l01);
            unsigned h23, l23;
            split2v(make_float2(va.z, va.w), h23, l23);
            *(uint2*)&s_ahi[(buf ^ 1) * MT * 72 + srow * 72 + scol] = make_uint2(h01, h23);
            *(uint2*)&s_alo[(buf ^ 1) * MT * 72 + srow * 72 + scol] = make_uint2(l01, l23);
            split2v(make_float2(vh.x, vh.y), h01, l01);
            split2v(make_float2(vh.z, vh.w), h23, l23);
            *(uint2*)&s_hhi[(buf ^ 1) * MT * 72 + srow * 72 + scol] = make_uint2(h01, h23);
            *(uint2*)&s_hlo[(buf ^ 1) * MT * 72 + srow * 72 + scol] = make_uint2(l01, l23);
            *(float4*)&s_hf[(buf ^ 1) * MT * 68 + srow * 68 + scol] = vh;
        }
        __syncthreads();
    }
}

// ---------------- mean pool + fc1(relu) + fc2 + log_softmax -----------------
__device__ __forceinline__ int lbound(const int* __restrict__ b, int v) {
    int lo = 0, hi = NN;
    while (lo < hi) {
        int m = (lo + hi) >> 1;
        if (b[m] < v) lo = m + 1; else hi = m;
    }
    return lo;
}

__global__ void k_poolfc(const int* __restrict__ batch,
                         const float* __restrict__ fc1w, const float* __restrict__ fc1b,
                         const float* __restrict__ fc2w, const float* __restrict__ fc2b,
                         float* __restrict__ out) {
    int g = threadIdx.x;
    if (g >= NG) return;
    int cnt = lbound(batch, g + 1) - lbound(batch, g);
    float inv = 1.f / fmaxf((float)cnt, 1.f);
    float p[D];
#pragma unroll
    for (int k = 0; k < D; k++) p[k] = g_pooled[g * D + k] * inv;

    float y[DH];
#pragma unroll
    for (int j = 0; j < DH; j++) {
        float s = fc1b[j];
#pragma unroll
        for (int k = 0; k < D; k++) s += p[k] * fc1w[j * D + k];
        y[j] = fmaxf(s, 0.f);
    }

    float z[NC];
    float mx = -1e30f;
#pragma unroll
    for (int c = 0; c < NC; c++) {
        float s = fc2b[c];
#pragma unroll
        for (int j = 0; j < DH; j++) s += y[j] * fc2w[c * DH + j];
        z[c] = s;
        mx = fmaxf(mx, s);
    }
    float lse = 0.f;
#pragma unroll
    for (int c = 0; c < NC; c++) lse += expf(z[c] - mx);
    lse = logf(lse) + mx;
#pragma unroll
    for (int c = 0; c < NC; c++) out[g * NC + c] = z[c] - lse;
}

// ---------------- launch -----------------------------------------------------
extern "C" void kernel_launch(void* const* d_in, const int* in_sizes, int n_in,
                              void* d_out, int out_size) {
    const float* x     = (const float*)d_in[0];
    const int*   ei    = (const int*)d_in[1];
    const int*   batch = (const int*)d_in[2];
    const float* W     = (const float*)d_in[3];
    const float* w_ih  = (const float*)d_in[4];
    const float* w_hh  = (const float*)d_in[5];
    const float* b_ih  = (const float*)d_in[6];
    const float* b_hh  = (const float*)d_in[7];
    const float* fc1w  = (const float*)d_in[8];
    const float* fc1b  = (const float*)d_in[9];
    const float* fc2w  = (const float*)d_in[10];
    const float* fc2b  = (const float*)d_in[11];
    float* out = (float*)d_out;

    cudaFuncSetAttribute(k_gates, cudaFuncAttributeMaxDynamicSharedMemorySize,
                         GATES_SMEM);

    k_init<<<32, 256>>>();

    for (int l = 0; l < 2; l++) {
        k_mgemm<<<592, 256>>>(x, W, l);
        k_scatter<<<(NE * 4 + 255) / 256, 256>>>(ei);
        k_gates<<<148, 512, GATES_SMEM>>>(x, w_ih, w_hh, b_ih, b_hh, batch, l);
    }
    k_poolfc<<<1, 128>>>(batch, fc1w, fc1b, fc2w, fc2b, out);
}

// round 14
// speedup vs baseline: 1.0934x; 1.0037x over previous
#include <cuda_runtime.h>
#include <cuda_bf16.h>
#include <math.h>

#define NN 50000
#define NE 800000
#define D  64
#define NG 128
#define DH 32
#define NC 6

// ---------------- scratch (device globals; no allocation allowed) ----------
__device__ float g_h[NN * D];       // hidden state
__device__ float g_m[NN * D];       // per-node messages m = h @ W[l]
__device__ float g_agg[NN * D];     // scatter-add destination
__device__ float g_pooled[NG * D];  // graph pooling sums

__device__ __forceinline__ float sigf(float x) {
    return __fdividef(1.f, 1.f + __expf(-x));
}
__device__ __forceinline__ float tanhfast(float x) {
    return __fdividef(2.f, 1.f + __expf(-2.f * x)) - 1.f;
}

// bf16 split helpers: v = hi + lo with |residual| ~ 2^-16 |v|
__device__ __forceinline__ void split1(float v, __nv_bfloat16& h, __nv_bfloat16& l) {
    h = __float2bfloat16(v);
    l = __float2bfloat16(v - __bfloat162float(h));
}
__device__ __forceinline__ void split_pair(float v0, float v1, unsigned& hi, unsigned& lo) {
    __nv_bfloat16 h0, l0, h1, l1;
    split1(v0, h0, l0);
    split1(v1, h1, l1);
    hi = (unsigned)__bfloat16_as_ushort(h0) | ((unsigned)__bfloat16_as_ushort(h1) << 16);
    lo = (unsigned)__bfloat16_as_ushort(l0) | ((unsigned)__bfloat16_as_ushort(l1) << 16);
}
// vector split: float2 -> (bf16x2 hi word, bf16x2 lo word)
__device__ __forceinline__ void split2v(float2 v, unsigned& hi, unsigned& lo) {
    __nv_bfloat162 h = __float22bfloat162_rn(v);
    float2 r = __bfloat1622float2(h);
    __nv_bfloat162 l = __float22bfloat162_rn(make_float2(v.x - r.x, v.y - r.y));
    hi = *(unsigned*)&h;
    lo = *(unsigned*)&l;
}

// mma.sync m16n8k16 bf16 -> f32 accumulate
__device__ __forceinline__ void mma16816(float* c, const unsigned* a, const unsigned* b) {
    asm volatile(
        "mma.sync.aligned.m16n8k16.row.col.f32.bf16.bf16.f32 "
        "{%0,%1,%2,%3}, {%4,%5,%6,%7}, {%8,%9}, {%0,%1,%2,%3};"
        : "+f"(c[0]), "+f"(c[1]), "+f"(c[2]), "+f"(c[3])
        : "r"(a[0]), "r"(a[1]), "r"(a[2]), "r"(a[3]), "r"(b[0]), "r"(b[1]));
}

// ldmatrix x4: loads a full 16x16 bf16 A-fragment (4 8x8 tiles) in one inst.
__device__ __forceinline__ void ldmat4(unsigned* r, unsigned addr) {
    asm volatile(
        "ldmatrix.sync.aligned.m8n8.x4.shared.b16 {%0,%1,%2,%3}, [%4];"
        : "=r"(r[0]), "=r"(r[1]), "=r"(r[2]), "=r"(r[3]) : "r"(addr));
}

// ---------------- init: zero pooled sums ------------------------------------
__global__ void k_init() {
    int i = blockIdx.x * 256 + threadIdx.x;
    if (i < NG * D) g_pooled[i] = 0.f;
}

// ---------------- m = h @ W[layer] via bf16x3 tensor cores; zeroes agg ------
// Double-buffered pipeline (unchanged from measured-good R10 version).
__global__ __launch_bounds__(256, 1)
void k_mgemm(const float* __restrict__ x, const float* __restrict__ W, int layer) {
    __shared__ __align__(16) __nv_bfloat16 s_hhi[2][16 * 72];
    __shared__ __align__(16) __nv_bfloat16 s_hlo[2][16 * 72];

    int tid = threadIdx.x;
    int wid = tid >> 5, lane = tid & 31;
    int tg = lane & 3, gid = lane >> 2;
    int dbase = wid * 8;
    int d0 = dbase + tg * 2;

    const float* Wl = W + layer * 64 * 64;
    unsigned Bhi[4][2], Blo[4][2];
#pragma unroll
    for (int kt = 0; kt < 4; kt++) {
        int k0 = kt * 16 + tg * 2;
        int nc = dbase + gid;
        split_pair(Wl[(k0)     * 64 + nc], Wl[(k0 + 1) * 64 + nc], Bhi[kt][0], Blo[kt][0]);
        split_pair(Wl[(k0 + 8) * 64 + nc], Wl[(k0 + 9) * 64 + nc], Bhi[kt][1], Blo[kt][1]);
    }

    const float* hin = layer ? g_h : x;
    int srow = tid >> 4;
    int scol = (tid & 15) * 4;
    const int stride = gridDim.x * 16;

    int chunk = blockIdx.x * 16;
    float4 vh;
    if (chunk < NN) {
        vh = *(const float4*)&hin[chunk * 64 + srow * 64 + scol];
        unsigned h01, l01, h23, l23;
        split2v(make_float2(vh.x, vh.y), h01, l01);
        split2v(make_float2(vh.z, vh.w), h23, l23);
        *(uint2*)&s_hhi[0][srow * 72 + scol] = make_uint2(h01, h23);
        *(uint2*)&s_hlo[0][srow * 72 + scol] = make_uint2(l01, l23);
    }
    __syncthreads();

    for (int it = 0; chunk < NN; chunk += stride, it++) {
        int buf = it & 1;
        int next = chunk + stride;
        if (next < NN)
            vh = *(const float4*)&hin[next * 64 + srow * 64 + scol];

        float C[4] = {0.f, 0.f, 0.f, 0.f};
#pragma unroll
        for (int kt = 0; kt < 4; kt++) {
            int k0 = kt * 16 + tg * 2;
            unsigned ahi[4], alo[4];
            ahi[0] = *(const unsigned*)&s_hhi[buf][(gid)     * 72 + k0];
            ahi[1] = *(const unsigned*)&s_hhi[buf][(gid + 8) * 72 + k0];
            ahi[2] = *(const unsigned*)&s_hhi[buf][(gid)     * 72 + k0 + 8];
            ahi[3] = *(const unsigned*)&s_hhi[buf][(gid + 8) * 72 + k0 + 8];
            alo[0] = *(const unsigned*)&s_hlo[buf][(gid)     * 72 + k0];
            alo[1] = *(const unsigned*)&s_hlo[buf][(gid + 8) * 72 + k0];
            alo[2] = *(const unsigned*)&s_hlo[buf][(gid)     * 72 + k0 + 8];
            alo[3] = *(const unsigned*)&s_hlo[buf][(gid + 8) * 72 + k0 + 8];
            mma16816(C, ahi, Bhi[kt]);
            mma16816(C, ahi, Blo[kt]);
            mma16816(C, alo, Bhi[kt]);
        }

#pragma unroll
        for (int p = 0; p < 2; p++) {
            int node = chunk + gid + p * 8;
            *(float2*)&g_m[node * 64 + d0] = make_float2(C[p * 2], C[p * 2 + 1]);
            *(float2*)&g_agg[node * 64 + d0] = make_float2(0.f, 0.f);
        }

        if (next < NN) {
            unsigned h01, l01, h23, l23;
            split2v(make_float2(vh.x, vh.y), h01, l01);
            split2v(make_float2(vh.z, vh.w), h23, l23);
            *(uint2*)&s_hhi[buf ^ 1][srow * 72 + scol] = make_uint2(h01, h23);
            *(uint2*)&s_hlo[buf ^ 1][srow * 72 + scol] = make_uint2(l01, l23);
        }
        __syncthreads();
    }
}

// ---------------- edge scatter: agg[dst] += m[src] --------------------------
// One thread per (4-edge group, 16B quad): int4 index loads amortize index
// traffic 4x; 4 independent gather->RED.128 chains per thread. (R13 proven)
__global__ void k_scatter(const int* __restrict__ ei) {
    int t = blockIdx.x * 256 + threadIdx.x;
    if (t >= NE * 4) return;
    int q = (t & 15) * 4;
    int eg = t >> 4;  // group of 4 consecutive edges
    int4 s4 = __ldg((const int4*)ei + eg);
    int4 d4 = __ldg((const int4*)(ei + NE) + eg);
    float4 v0 = *(const float4*)&g_m[s4.x * 64 + q];
    float4 v1 = *(const float4*)&g_m[s4.y * 64 + q];
    float4 v2 = *(const float4*)&g_m[s4.z * 64 + q];
    float4 v3 = *(const float4*)&g_m[s4.w * 64 + q];
    atomicAdd((float4*)&g_agg[d4.x * 64 + q], v0);
    atomicAdd((float4*)&g_agg[d4.y * 64 + q], v1);
    atomicAdd((float4*)&g_agg[d4.z * 64 + q], v2);
    atomicAdd((float4*)&g_agg[d4.w * 64 + q], v3);
}

// ---------------- fused GRU gates, 16-warp split, 32-node M-tile ------------
// R13 structure + ldmatrix.x4 fragment loads (2 ldmatrix replace 8 LDS.32
// per (kt,rb) fragment pair -> 4x fewer shared-load instructions in the
// MMA hot loop).
#define MT 32
#define GATES_SMEM (4 * (2 * MT * 72) * 2 + 2 * MT * 68 * 4 + 6 * MT * 72 * 4)

__global__ __launch_bounds__(512, 1)
void k_gates(const float* __restrict__ x,
             const float* __restrict__ w_ih, const float* __restrict__ w_hh,
             const float* __restrict__ b_ih, const float* __restrict__ b_hh,
             const int* __restrict__ batch, int layer) {
    extern __shared__ __align__(16) char smraw[];
    __nv_bfloat16* s_ahi = (__nv_bfloat16*)smraw;      // [2][MT*72]
    __nv_bfloat16* s_alo = s_ahi + 2 * MT * 72;
    __nv_bfloat16* s_hhi = s_alo + 2 * MT * 72;
    __nv_bfloat16* s_hlo = s_hhi + 2 * MT * 72;
    float* s_hf = (float*)(s_hlo + 2 * MT * 72);       // [2][MT*68]
    float* sC   = s_hf + 2 * MT * 68;                  // [6][MT*72]

    int tid = threadIdx.x;
    int wid = tid >> 5, lane = tid & 31;
    int side = wid >> 3, w8 = wid & 7;
    int tg = lane & 3, gid = lane >> 2;
    int d0 = w8 * 8 + tg * 2;

    const float* wm = side ? w_hh : w_ih;
    unsigned Bhi[3][4][2], Blo[3][4][2];
#pragma unroll
    for (int g = 0; g < 3; g++) {
        const float* wr = wm + (g * 64 + w8 * 8 + gid) * 64;
#pragma unroll
        for (int kt = 0; kt < 4; kt++) {
            int k0 = kt * 16 + tg * 2;
            split_pair(wr[k0],     wr[k0 + 1], Bhi[g][kt][0], Blo[g][kt][0]);
            split_pair(wr[k0 + 8], wr[k0 + 9], Bhi[g][kt][1], Blo[g][kt][1]);
        }
    }

    int srow = tid >> 4;          // 0..31
    int scol = (tid & 15) * 4;
    int erow = tid >> 5;          // 0..15
    int ecol = lane * 2;
    float2 ebi0 = *(const float2*)&b_ih[ecol];
    float2 ebi1 = *(const float2*)&b_ih[64 + ecol];
    float2 ebi2 = *(const float2*)&b_ih[128 + ecol];
    float2 ebh0 = *(const float2*)&b_hh[ecol];
    float2 ebh1 = *(const float2*)&b_hh[64 + ecol];
    float2 ebh2 = *(const float2*)&b_hh[128 + ecol];

    const float* hin = layer ? g_h : x;
    const __nv_bfloat16* pAhi = side ? s_hhi : s_ahi;
    const __nv_bfloat16* pAlo = side ? s_hlo : s_alo;
    const int stride = gridDim.x * MT;

    // ldmatrix per-lane address components: lane -> (tile row, tile col-half)
    //   tiles ordered [r0..7,k0..7],[r8..15,k0..7],[r0..7,k8..15],[r8..15,k8..15]
    unsigned lrow = (lane & 7) + ((lane >> 3) & 1) * 8;  // 0..15
    unsigned lcol = (lane >> 4) * 8;                     // 0 or 8
    unsigned base_ahi = (unsigned)__cvta_generic_to_shared(pAhi);
    unsigned base_alo = (unsigned)__cvta_generic_to_shared(pAlo);

    int chunk = blockIdx.x * MT;
    float4 va, vh;
    if (chunk + srow < NN) {
        va = *(const float4*)&g_agg[(chunk + srow) * 64 + scol];
        vh = *(const float4*)&hin[(chunk + srow) * 64 + scol];
        unsigned h01, l01, h23, l23;
        split2v(make_float2(va.x, va.y), h01, l01);
        split2v(make_float2(va.z, va.w), h23, l23);
        *(uint2*)&s_ahi[srow * 72 + scol] = make_uint2(h01, h23);
        *(uint2*)&s_alo[srow * 72 + scol] = make_uint2(l01, l23);
        split2v(make_float2(vh.x, vh.y), h01, l01);
        split2v(make_float2(vh.z, vh.w), h23, l23);
        *(uint2*)&s_hhi[srow * 72 + scol] = make_uint2(h01, h23);
        *(uint2*)&s_hlo[srow * 72 + scol] = make_uint2(l01, l23);
        *(float4*)&s_hf[srow * 68 + scol] = vh;
    }
    __syncthreads();

    for (int it = 0; chunk < NN; chunk += stride, it++) {
        int buf = it & 1;
        int abase = buf * MT * 72;
        int next = chunk + stride;
        if (next + srow < NN) {
            va = *(const float4*)&g_agg[(next + srow) * 64 + scol];
            vh = *(const float4*)&hin[(next + srow) * 64 + scol];
        }

        float C[3][2][4];
#pragma unroll
        for (int g = 0; g < 3; g++)
#pragma unroll
            for (int rb = 0; rb < 2; rb++)
#pragma unroll
                for (int q = 0; q < 4; q++) C[g][rb][q] = 0.f;

#pragma unroll
        for (int kt = 0; kt < 4; kt++) {
#pragma unroll
            for (int rb = 0; rb < 2; rb++) {
                unsigned off = (unsigned)((abase + (rb * 16 + lrow) * 72 +
                                           kt * 16 + lcol) * 2);
                unsigned ahi[4], alo[4];
                ldmat4(ahi, base_ahi + off);
                ldmat4(alo, base_alo + off);
#pragma unroll
                for (int g = 0; g < 3; g++) {
                    mma16816(C[g][rb], ahi, Bhi[g][kt]);
                    mma16816(C[g][rb], ahi, Blo[g][kt]);
                    mma16816(C[g][rb], alo, Bhi[g][kt]);
                }
            }
        }

#pragma unroll
        for (int g = 0; g < 3; g++)
#pragma unroll
            for (int rb = 0; rb < 2; rb++)
#pragma unroll
                for (int p = 0; p < 2; p++)
                    *(float2*)&sC[((side * 3 + g) * MT + rb * 16 + gid + p * 8) * 72 + d0] =
                        make_float2(C[g][rb][2 * p], C[g][rb][2 * p + 1]);
        __syncthreads();

#pragma unroll
        for (int rr = 0; rr < 2; rr++) {
            int row = erow + rr * 16;
            int node = chunk + row;
            if (node < NN) {
                float2 ir = *(float2*)&sC[(0 * MT + row) * 72 + ecol];
                float2 iz = *(float2*)&sC[(1 * MT + row) * 72 + ecol];
                float2 ix = *(float2*)&sC[(2 * MT + row) * 72 + ecol];
                float2 hr = *(float2*)&sC[(3 * MT + row) * 72 + ecol];
                float2 hz = *(float2*)&sC[(4 * MT + row) * 72 + ecol];
                float2 hn = *(float2*)&sC[(5 * MT + row) * 72 + ecol];
                float2 ho = *(float2*)&s_hf[buf * MT * 68 + row * 68 + ecol];

                float r0 = sigf(ir.x + ebi0.x + hr.x + ebh0.x);
                float z0 = sigf(iz.x + ebi1.x + hz.x + ebh1.x);
                float n0 = tanhfast(ix.x + ebi2.x + r0 * (hn.x + ebh2.x));
                float h0 = (1.f - z0) * n0 + z0 * ho.x;
                float r1 = sigf(ir.y + ebi0.y + hr.y + ebh0.y);
                float z1 = sigf(iz.y + ebi1.y + hz.y + ebh1.y);
                float n1 = tanhfast(ix.y + ebi2.y + r1 * (hn.y + ebh2.y));
                float h1 = (1.f - z1) * n1 + z1 * ho.y;

                if (layer == 0) {
                    *(float2*)&g_h[node * 64 + ecol] = make_float2(h0, h1);
                } else {
                    float2 rv = make_float2(fmaxf(h0, 0.f), fmaxf(h1, 0.f));
                    atomicAdd((float2*)&g_pooled[batch[node] * 64 + ecol], rv);
                }
            }
        }

        if (next + srow < NN) {
            unsigned h01, l01;
            split2v(make_float2(va.x, va.y), h01, l01);
            unsigned h23, l23;
            split2v(make_float2(va.z, va.w), h23, l23);
            *(uint2*)&s_ahi[(buf ^ 1) * MT * 72 + srow * 72 + scol] = make_uint2(h01, h23);
            *(uint2*)&s_alo[(buf ^ 1) * MT * 72 + srow * 72 + scol] = make_uint2(l01, l23);
            split2v(make_float2(vh.x, vh.y), h01, l01);
            split2v(make_float2(vh.z, vh.w), h23, l23);
            *(uint2*)&s_hhi[(buf ^ 1) * MT * 72 + srow * 72 + scol] = make_uint2(h01, h23);
            *(uint2*)&s_hlo[(buf ^ 1) * MT * 72 + srow * 72 + scol] = make_uint2(l01, l23);
            *(float4*)&s_hf[(buf ^ 1) * MT * 68 + srow * 68 + scol] = vh;
        }
        __syncthreads();
    }
}

// ---------------- mean pool + fc1(relu) + fc2 + log_softmax -----------------
__device__ __forceinline__ int lbound(const int* __restrict__ b, int v) {
    int lo = 0, hi = NN;
    while (lo < hi) {
        int m = (lo + hi) >> 1;
        if (b[m] < v) lo = m + 1; else hi = m;
    }
    return lo;
}

__global__ void k_poolfc(const int* __restrict__ batch,
                         const float* __restrict__ fc1w, const float* __restrict__ fc1b,
                         const float* __restrict__ fc2w, const float* __restrict__ fc2b,
                         float* __restrict__ out) {
    int g = threadIdx.x;
    if (g >= NG) return;
    int cnt = lbound(batch, g + 1) - lbound(batch, g);
    float inv = 1.f / fmaxf((float)cnt, 1.f);
    float p[D];
#pragma unroll
    for (int k = 0; k < D; k++) p[k] = g_pooled[g * D + k] * inv;

    float y[DH];
#pragma unroll
    for (int j = 0; j < DH; j++) {
        float s = fc1b[j];
#pragma unroll
        for (int k = 0; k < D; k++) s += p[k] * fc1w[j * D + k];
        y[j] = fmaxf(s, 0.f);
    }

    float z[NC];
    float mx = -1e30f;
#pragma unroll
    for (int c = 0; c < NC; c++) {
        float s = fc2b[c];
#pragma unroll
        for (int j = 0; j < DH; j++) s += y[j] * fc2w[c * DH + j];
        z[c] = s;
        mx = fmaxf(mx, s);
    }
    float lse = 0.f;
#pragma unroll
    for (int c = 0; c < NC; c++) lse += expf(z[c] - mx);
    lse = logf(lse) + mx;
#pragma unroll
    for (int c = 0; c < NC; c++) out[g * NC + c] = z[c] - lse;
}

// ---------------- launch -----------------------------------------------------
extern "C" void kernel_launch(void* const* d_in, const int* in_sizes, int n_in,
                              void* d_out, int out_size) {
    const float* x     = (const float*)d_in[0];
    const int*   ei    = (const int*)d_in[1];
    const int*   batch = (const int*)d_in[2];
    const float* W     = (const float*)d_in[3];
    const float* w_ih  = (const float*)d_in[4];
    const float* w_hh  = (const float*)d_in[5];
    const float* b_ih  = (const float*)d_in[6];
    const float* b_hh  = (const float*)d_in[7];
    const float* fc1w  = (const float*)d_in[8];
    const float* fc1b  = (const float*)d_in[9];
    const float* fc2w  = (const float*)d_in[10];
    const float* fc2b  = (const float*)d_in[11];
    float* out = (float*)d_out;

    cudaFuncSetAttribute(k_gates, cudaFuncAttributeMaxDynamicSharedMemorySize,
                         GATES_SMEM);

    k_init<<<32, 256>>>();

    for (int l = 0; l < 2; l++) {
        k_mgemm<<<592, 256>>>(x, W, l);
        k_scatter<<<(NE * 4 + 255) / 256, 256>>>(ei);
        k_gates<<<148, 512, GATES_SMEM>>>(x, w_ih, w_hh, b_ih, b_hh, batch, l);
    }
    k_poolfc<<<1, 128>>>(batch, fc1w, fc1b, fc2w, fc2b, out);
}

// round 16
// speedup vs baseline: 1.1190x; 1.0234x over previous
#include <cuda_runtime.h>
#include <cuda_bf16.h>
#include <math.h>

#define NN 50000
#define NE 800000
#define D  64
#define NG 128
#define DH 32
#define NC 6

// ---------------- scratch (device globals; no allocation allowed) ----------
__device__ float         g_h[NN * D];    // hidden state
__device__ __nv_bfloat16 g_m[NN * D];    // messages m = h @ W[l], bf16 (halves scatter gather bytes)
__device__ float         g_agg[NN * D];  // scatter-add destination (f32 atomics)
__device__ float         g_pooled[NG * D];

__device__ __forceinline__ float sigf(float x) {
    return __fdividef(1.f, 1.f + __expf(-x));
}
__device__ __forceinline__ float tanhfast(float x) {
    return __fdividef(2.f, 1.f + __expf(-2.f * x)) - 1.f;
}

// bf16 split helpers: v = hi + lo with |residual| ~ 2^-16 |v|
__device__ __forceinline__ void split1(float v, __nv_bfloat16& h, __nv_bfloat16& l) {
    h = __float2bfloat16(v);
    l = __float2bfloat16(v - __bfloat162float(h));
}
__device__ __forceinline__ void split_pair(float v0, float v1, unsigned& hi, unsigned& lo) {
    __nv_bfloat16 h0, l0, h1, l1;
    split1(v0, h0, l0);
    split1(v1, h1, l1);
    hi = (unsigned)__bfloat16_as_ushort(h0) | ((unsigned)__bfloat16_as_ushort(h1) << 16);
    lo = (unsigned)__bfloat16_as_ushort(l0) | ((unsigned)__bfloat16_as_ushort(l1) << 16);
}
__device__ __forceinline__ void split2v(float2 v, unsigned& hi, unsigned& lo) {
    __nv_bfloat162 h = __float22bfloat162_rn(v);
    float2 r = __bfloat1622float2(h);
    __nv_bfloat162 l = __float22bfloat162_rn(make_float2(v.x - r.x, v.y - r.y));
    hi = *(unsigned*)&h;
    lo = *(unsigned*)&l;
}
__device__ __forceinline__ float4 bf8_to_f4(uint2 u) {
    float2 a = __bfloat1622float2(*(__nv_bfloat162*)&u.x);
    float2 b = __bfloat1622float2(*(__nv_bfloat162*)&u.y);
    return make_float4(a.x, a.y, b.x, b.y);
}

// mma.sync m16n8k16 bf16 -> f32 accumulate
__device__ __forceinline__ void mma16816(float* c, const unsigned* a, const unsigned* b) {
    asm volatile(
        "mma.sync.aligned.m16n8k16.row.col.f32.bf16.bf16.f32 "
        "{%0,%1,%2,%3}, {%4,%5,%6,%7}, {%8,%9}, {%0,%1,%2,%3};"
        : "+f"(c[0]), "+f"(c[1]), "+f"(c[2]), "+f"(c[3])
        : "r"(a[0]), "r"(a[1]), "r"(a[2]), "r"(a[3]), "r"(b[0]), "r"(b[1]));
}

// ldmatrix x4: full 16x16 bf16 A-fragment in one instruction.
__device__ __forceinline__ void ldmat4(unsigned* r, unsigned addr) {
    asm volatile(
        "ldmatrix.sync.aligned.m8n8.x4.shared.b16 {%0,%1,%2,%3}, [%4];"
        : "=r"(r[0]), "=r"(r[1]), "=r"(r[2]), "=r"(r[3]) : "r"(addr));
}

// ---------------- init: zero pooled sums ------------------------------------
__global__ void k_init() {
    int i = blockIdx.x * 256 + threadIdx.x;
    if (i < NG * D) g_pooled[i] = 0.f;
}

// ---------------- m = h @ W[layer] via bf16x3 tensor cores; zeroes agg ------
// Double-buffered pipeline; m written as bf16x2 (4B per 2 dims).
__global__ __launch_bounds__(256, 1)
void k_mgemm(const float* __restrict__ x, const float* __restrict__ W, int layer) {
    __shared__ __align__(16) __nv_bfloat16 s_hhi[2][16 * 72];
    __shared__ __align__(16) __nv_bfloat16 s_hlo[2][16 * 72];

    int tid = threadIdx.x;
    int wid = tid >> 5, lane = tid & 31;
    int tg = lane & 3, gid = lane >> 2;
    int dbase = wid * 8;
    int d0 = dbase + tg * 2;

    const float* Wl = W + layer * 64 * 64;
    unsigned Bhi[4][2], Blo[4][2];
#pragma unroll
    for (int kt = 0; kt < 4; kt++) {
        int k0 = kt * 16 + tg * 2;
        int nc = dbase + gid;
        split_pair(Wl[(k0)     * 64 + nc], Wl[(k0 + 1) * 64 + nc], Bhi[kt][0], Blo[kt][0]);
        split_pair(Wl[(k0 + 8) * 64 + nc], Wl[(k0 + 9) * 64 + nc], Bhi[kt][1], Blo[kt][1]);
    }

    const float* hin = layer ? g_h : x;
    int srow = tid >> 4;
    int scol = (tid & 15) * 4;
    const int stride = gridDim.x * 16;

    int chunk = blockIdx.x * 16;
    float4 vh;
    if (chunk < NN) {
        vh = *(const float4*)&hin[chunk * 64 + srow * 64 + scol];
        unsigned h01, l01, h23, l23;
        split2v(make_float2(vh.x, vh.y), h01, l01);
        split2v(make_float2(vh.z, vh.w), h23, l23);
        *(uint2*)&s_hhi[0][srow * 72 + scol] = make_uint2(h01, h23);
        *(uint2*)&s_hlo[0][srow * 72 + scol] = make_uint2(l01, l23);
    }
    __syncthreads();

    for (int it = 0; chunk < NN; chunk += stride, it++) {
        int buf = it & 1;
        int next = chunk + stride;
        if (next < NN)
            vh = *(const float4*)&hin[next * 64 + srow * 64 + scol];

        float C[4] = {0.f, 0.f, 0.f, 0.f};
#pragma unroll
        for (int kt = 0; kt < 4; kt++) {
            int k0 = kt * 16 + tg * 2;
            unsigned ahi[4], alo[4];
            ahi[0] = *(const unsigned*)&s_hhi[buf][(gid)     * 72 + k0];
            ahi[1] = *(const unsigned*)&s_hhi[buf][(gid + 8) * 72 + k0];
            ahi[2] = *(const unsigned*)&s_hhi[buf][(gid)     * 72 + k0 + 8];
            ahi[3] = *(const unsigned*)&s_hhi[buf][(gid + 8) * 72 + k0 + 8];
            alo[0] = *(const unsigned*)&s_hlo[buf][(gid)     * 72 + k0];
            alo[1] = *(const unsigned*)&s_hlo[buf][(gid + 8) * 72 + k0];
            alo[2] = *(const unsigned*)&s_hlo[buf][(gid)     * 72 + k0 + 8];
            alo[3] = *(const unsigned*)&s_hlo[buf][(gid + 8) * 72 + k0 + 8];
            mma16816(C, ahi, Bhi[kt]);
            mma16816(C, ahi, Blo[kt]);
            mma16816(C, alo, Bhi[kt]);
        }

#pragma unroll
        for (int p = 0; p < 2; p++) {
            int node = chunk + gid + p * 8;
            __nv_bfloat162 mv = __float22bfloat162_rn(make_float2(C[p * 2], C[p * 2 + 1]));
            *(__nv_bfloat162*)&g_m[node * 64 + d0] = mv;
            *(float2*)&g_agg[node * 64 + d0] = make_float2(0.f, 0.f);
        }

        if (next < NN) {
            unsigned h01, l01, h23, l23;
            split2v(make_float2(vh.x, vh.y), h01, l01);
            split2v(make_float2(vh.z, vh.w), h23, l23);
            *(uint2*)&s_hhi[buf ^ 1][srow * 72 + scol] = make_uint2(h01, h23);
            *(uint2*)&s_hlo[buf ^ 1][srow * 72 + scol] = make_uint2(l01, l23);
        }
        __syncthreads();
    }
}

// ---------------- edge scatter: agg[dst] += m[src] --------------------------
// One thread per (4-edge group, quad): bf16 gather (8B/quad, halved traffic),
// f32 RED.128. int4 index loads amortize index traffic 4x. Lanes 0-15 cover
// one edge group's 16 quads -> 128B coalesced row reads.
__global__ void k_scatter(const int* __restrict__ ei) {
    int t = blockIdx.x * 256 + threadIdx.x;
    if (t >= NE * 4) return;
    int q = (t & 15) * 4;
    int eg = t >> 4;
    int4 s4 = __ldg((const int4*)ei + eg);
    int4 d4 = __ldg((const int4*)(ei + NE) + eg);
    uint2 u0 = *(const uint2*)&g_m[s4.x * 64 + q];
    uint2 u1 = *(const uint2*)&g_m[s4.y * 64 + q];
    uint2 u2 = *(const uint2*)&g_m[s4.z * 64 + q];
    uint2 u3 = *(const uint2*)&g_m[s4.w * 64 + q];
    atomicAdd((float4*)&g_agg[d4.x * 64 + q], bf8_to_f4(u0));
    atomicAdd((float4*)&g_agg[d4.y * 64 + q], bf8_to_f4(u1));
    atomicAdd((float4*)&g_agg[d4.z * 64 + q], bf8_to_f4(u2));
    atomicAdd((float4*)&g_agg[d4.w * 64 + q], bf8_to_f4(u3));
}

// ---------------- fused GRU gates, 16-warp split, 32-node M-tile ------------
// (R14 proven form: ldmatrix.x4 fragment loads, warp-split gate ownership)
#define MT 32
#define GATES_SMEM (4 * (2 * MT * 72) * 2 + 2 * MT * 68 * 4 + 6 * MT * 72 * 4)

__global__ __launch_bounds__(512, 1)
void k_gates(const float* __restrict__ x,
             const float* __restrict__ w_ih, const float* __restrict__ w_hh,
             const float* __restrict__ b_ih, const float* __restrict__ b_hh,
             const int* __restrict__ batch, int layer) {
    extern __shared__ __align__(16) char smraw[];
    __nv_bfloat16* s_ahi = (__nv_bfloat16*)smraw;      // [2][MT*72]
    __nv_bfloat16* s_alo = s_ahi + 2 * MT * 72;
    __nv_bfloat16* s_hhi = s_alo + 2 * MT * 72;
    __nv_bfloat16* s_hlo = s_hhi + 2 * MT * 72;
    float* s_hf = (float*)(s_hlo + 2 * MT * 72);       // [2][MT*68]
    float* sC   = s_hf + 2 * MT * 68;                  // [6][MT*72]

    int tid = threadIdx.x;
    int wid = tid >> 5, lane = tid & 31;
    int side = wid >> 3, w8 = wid & 7;
    int tg = lane & 3, gid = lane >> 2;
    int d0 = w8 * 8 + tg * 2;

    const float* wm = side ? w_hh : w_ih;
    unsigned Bhi[3][4][2], Blo[3][4][2];
#pragma unroll
    for (int g = 0; g < 3; g++) {
        const float* wr = wm + (g * 64 + w8 * 8 + gid) * 64;
#pragma unroll
        for (int kt = 0; kt < 4; kt++) {
            int k0 = kt * 16 + tg * 2;
            split_pair(wr[k0],     wr[k0 + 1], Bhi[g][kt][0], Blo[g][kt][0]);
            split_pair(wr[k0 + 8], wr[k0 + 9], Bhi[g][kt][1], Blo[g][kt][1]);
        }
    }

    int srow = tid >> 4;          // 0..31
    int scol = (tid & 15) * 4;
    int erow = tid >> 5;          // 0..15
    int ecol = lane * 2;
    float2 ebi0 = *(const float2*)&b_ih[ecol];
    float2 ebi1 = *(const float2*)&b_ih[64 + ecol];
    float2 ebi2 = *(const float2*)&b_ih[128 + ecol];
    float2 ebh0 = *(const float2*)&b_hh[ecol];
    float2 ebh1 = *(const float2*)&b_hh[64 + ecol];
    float2 ebh2 = *(const float2*)&b_hh[128 + ecol];

    const float* hin = layer ? g_h : x;
    const __nv_bfloat16* pAhi = side ? s_hhi : s_ahi;
    const __nv_bfloat16* pAlo = side ? s_hlo : s_alo;
    const int stride = gridDim.x * MT;

    unsigned lrow = (lane & 7) + ((lane >> 3) & 1) * 8;  // 0..15
    unsigned lcol = (lane >> 4) * 8;                     // 0 or 8
    unsigned base_ahi = (unsigned)__cvta_generic_to_shared(pAhi);
    unsigned base_alo = (unsigned)__cvta_generic_to_shared(pAlo);

    int chunk = blockIdx.x * MT;
    float4 va, vh;
    if (chunk + srow < NN) {
        va = *(const float4*)&g_agg[(chunk + srow) * 64 + scol];
        vh = *(const float4*)&hin[(chunk + srow) * 64 + scol];
        unsigned h01, l01, h23, l23;
        split2v(make_float2(va.x, va.y), h01, l01);
        split2v(make_float2(va.z, va.w), h23, l23);
        *(uint2*)&s_ahi[srow * 72 + scol] = make_uint2(h01, h23);
        *(uint2*)&s_alo[srow * 72 + scol] = make_uint2(l01, l23);
        split2v(make_float2(vh.x, vh.y), h01, l01);
        split2v(make_float2(vh.z, vh.w), h23, l23);
        *(uint2*)&s_hhi[srow * 72 + scol] = make_uint2(h01, h23);
        *(uint2*)&s_hlo[srow * 72 + scol] = make_uint2(l01, l23);
        *(float4*)&s_hf[srow * 68 + scol] = vh;
    }
    __syncthreads();

    for (int it = 0; chunk < NN; chunk += stride, it++) {
        int buf = it & 1;
        int abase = buf * MT * 72;
        int next = chunk + stride;
        if (next + srow < NN) {
            va = *(const float4*)&g_agg[(next + srow) * 64 + scol];
            vh = *(const float4*)&hin[(next + srow) * 64 + scol];
        }

        float C[3][2][4];
#pragma unroll
        for (int g = 0; g < 3; g++)
#pragma unroll
            for (int rb = 0; rb < 2; rb++)
#pragma unroll
                for (int q = 0; q < 4; q++) C[g][rb][q] = 0.f;

#pragma unroll
        for (int kt = 0; kt < 4; kt++) {
#pragma unroll
            for (int rb = 0; rb < 2; rb++) {
                unsigned off = (unsigned)((abase + (rb * 16 + lrow) * 72 +
                                           kt * 16 + lcol) * 2);
                unsigned ahi[4], alo[4];
                ldmat4(ahi, base_ahi + off);
                ldmat4(alo, base_alo + off);
#pragma unroll
                for (int g = 0; g < 3; g++) {
                    mma16816(C[g][rb], ahi, Bhi[g][kt]);
                    mma16816(C[g][rb], ahi, Blo[g][kt]);
                    mma16816(C[g][rb], alo, Bhi[g][kt]);
                }
            }
        }

#pragma unroll
        for (int g = 0; g < 3; g++)
#pragma unroll
            for (int rb = 0; rb < 2; rb++)
#pragma unroll
                for (int p = 0; p < 2; p++)
                    *(float2*)&sC[((side * 3 + g) * MT + rb * 16 + gid + p * 8) * 72 + d0] =
                        make_float2(C[g][rb][2 * p], C[g][rb][2 * p + 1]);
        __syncthreads();

#pragma unroll
        for (int rr = 0; rr < 2; rr++) {
            int row = erow + rr * 16;
            int node = chunk + row;
            if (node < NN) {
                float2 ir = *(float2*)&sC[(0 * MT + row) * 72 + ecol];
                float2 iz = *(float2*)&sC[(1 * MT + row) * 72 + ecol];
                float2 ix = *(float2*)&sC[(2 * MT + row) * 72 + ecol];
                float2 hr = *(float2*)&sC[(3 * MT + row) * 72 + ecol];
                float2 hz = *(float2*)&sC[(4 * MT + row) * 72 + ecol];
                float2 hn = *(float2*)&sC[(5 * MT + row) * 72 + ecol];
                float2 ho = *(float2*)&s_hf[buf * MT * 68 + row * 68 + ecol];

                float r0 = sigf(ir.x + ebi0.x + hr.x + ebh0.x);
                float z0 = sigf(iz.x + ebi1.x + hz.x + ebh1.x);
                float n0 = tanhfast(ix.x + ebi2.x + r0 * (hn.x + ebh2.x));
                float h0 = (1.f - z0) * n0 + z0 * ho.x;
                float r1 = sigf(ir.y + ebi0.y + hr.y + ebh0.y);
                float z1 = sigf(iz.y + ebi1.y + hz.y + ebh1.y);
                float n1 = tanhfast(ix.y + ebi2.y + r1 * (hn.y + ebh2.y));
                float h1 = (1.f - z1) * n1 + z1 * ho.y;

                if (layer == 0) {
                    *(float2*)&g_h[node * 64 + ecol] = make_float2(h0, h1);
                } else {
                    float2 rv = make_float2(fmaxf(h0, 0.f), fmaxf(h1, 0.f));
                    atomicAdd((float2*)&g_pooled[batch[node] * 64 + ecol], rv);
                }
            }
        }

        if (next + srow < NN) {
            unsigned h01, l01;
            split2v(make_float2(va.x, va.y), h01, l01);
            unsigned h23, l23;
            split2v(make_float2(va.z, va.w), h23, l23);
            *(uint2*)&s_ahi[(buf ^ 1) * MT * 72 + srow * 72 + scol] = make_uint2(h01, h23);
            *(uint2*)&s_alo[(buf ^ 1) * MT * 72 + srow * 72 + scol] = make_uint2(l01, l23);
            split2v(make_float2(vh.x, vh.y), h01, l01);
            split2v(make_float2(vh.z, vh.w), h23, l23);
            *(uint2*)&s_hhi[(buf ^ 1) * MT * 72 + srow * 72 + scol] = make_uint2(h01, h23);
            *(uint2*)&s_hlo[(buf ^ 1) * MT * 72 + srow * 72 + scol] = make_uint2(l01, l23);
            *(float4*)&s_hf[(buf ^ 1) * MT * 68 + srow * 68 + scol] = vh;
        }
        __syncthreads();
    }
}

// ---------------- mean pool + fc1(relu) + fc2 + log_softmax -----------------
__device__ __forceinline__ int lbound(const int* __restrict__ b, int v) {
    int lo = 0, hi = NN;
    while (lo < hi) {
        int m = (lo + hi) >> 1;
        if (b[m] < v) lo = m + 1; else hi = m;
    }
    return lo;
}

__global__ void k_poolfc(const int* __restrict__ batch,
                         const float* __restrict__ fc1w, const float* __restrict__ fc1b,
                         const float* __restrict__ fc2w, const float* __restrict__ fc2b,
                         float* __restrict__ out) {
    int g = threadIdx.x;
    if (g >= NG) return;
    int cnt = lbound(batch, g + 1) - lbound(batch, g);
    float inv = 1.f / fmaxf((float)cnt, 1.f);
    float p[D];
#pragma unroll
    for (int k = 0; k < D; k++) p[k] = g_pooled[g * D + k] * inv;

    float y[DH];
#pragma unroll
    for (int j = 0; j < DH; j++) {
        float s = fc1b[j];
#pragma unroll
        for (int k = 0; k < D; k++) s += p[k] * fc1w[j * D + k];
        y[j] = fmaxf(s, 0.f);
    }

    float z[NC];
    float mx = -1e30f;
#pragma unroll
    for (int c = 0; c < NC; c++) {
        float s = fc2b[c];
#pragma unroll
        for (int j = 0; j < DH; j++) s += y[j] * fc2w[c * DH + j];
        z[c] = s;
        mx = fmaxf(mx, s);
    }
    float lse = 0.f;
#pragma unroll
    for (int c = 0; c < NC; c++) lse += expf(z[c] - mx);
    lse = logf(lse) + mx;
#pragma unroll
    for (int c = 0; c < NC; c++) out[g * NC + c] = z[c] - lse;
}

// ---------------- launch -----------------------------------------------------
extern "C" void kernel_launch(void* const* d_in, const int* in_sizes, int n_in,
                              void* d_out, int out_size) {
    const float* x     = (const float*)d_in[0];
    const int*   ei    = (const int*)d_in[1];
    const int*   batch = (const int*)d_in[2];
    const float* W     = (const float*)d_in[3];
    const float* w_ih  = (const float*)d_in[4];
    const float* w_hh  = (const float*)d_in[5];
    const float* b_ih  = (const float*)d_in[6];
    const float* b_hh  = (const float*)d_in[7];
    const float* fc1w  = (const float*)d_in[8];
    const float* fc1b  = (const float*)d_in[9];
    const float* fc2w  = (const float*)d_in[10];
    const float* fc2b  = (const float*)d_in[11];
    float* out = (float*)d_out;

    cudaFuncSetAttribute(k_gates, cudaFuncAttributeMaxDynamicSharedMemorySize,
                         GATES_SMEM);

    k_init<<<32, 256>>>();

    for (int l = 0; l < 2; l++) {
        k_mgemm<<<592, 256>>>(x, W, l);
        k_scatter<<<(NE * 4 + 255) / 256, 256>>>(ei);
        k_gates<<<148, 512, GATES_SMEM>>>(x, w_ih, w_hh, b_ih, b_hh, batch, l);
    }
    k_poolfc<<<1, 128>>>(batch, fc1w, fc1b, fc2w, fc2b, out);
}

// round 17
// speedup vs baseline: 1.3943x; 1.2460x over previous
#include <cuda_runtime.h>
#include <cuda_bf16.h>
#include <math.h>

#define NN 50000
#define NE 800000
#define D  64
#define NG 128
#define DH 32
#define NC 6

// ---------------- scratch (device globals; no allocation allowed) ----------
__device__ float         g_h[NN * D];    // hidden state
__device__ __nv_bfloat16 g_m[NN * D];    // messages m = h @ W[l], bf16
__device__ __nv_bfloat16 g_agg[NN * D];  // scatter-add destination, bf16 (vector RED)
__device__ float         g_pooled[NG * D];

__device__ __forceinline__ float sigf(float x) {
    return __fdividef(1.f, 1.f + __expf(-x));
}
__device__ __forceinline__ float tanhfast(float x) {
    return __fdividef(2.f, 1.f + __expf(-2.f * x)) - 1.f;
}

// bf16 split helpers: v = hi + lo with |residual| ~ 2^-16 |v|
__device__ __forceinline__ void split1(float v, __nv_bfloat16& h, __nv_bfloat16& l) {
    h = __float2bfloat16(v);
    l = __float2bfloat16(v - __bfloat162float(h));
}
__device__ __forceinline__ void split_pair(float v0, float v1, unsigned& hi, unsigned& lo) {
    __nv_bfloat16 h0, l0, h1, l1;
    split1(v0, h0, l0);
    split1(v1, h1, l1);
    hi = (unsigned)__bfloat16_as_ushort(h0) | ((unsigned)__bfloat16_as_ushort(h1) << 16);
    lo = (unsigned)__bfloat16_as_ushort(l0) | ((unsigned)__bfloat16_as_ushort(l1) << 16);
}
__device__ __forceinline__ void split2v(float2 v, unsigned& hi, unsigned& lo) {
    __nv_bfloat162 h = __float22bfloat162_rn(v);
    float2 r = __bfloat1622float2(h);
    __nv_bfloat162 l = __float22bfloat162_rn(make_float2(v.x - r.x, v.y - r.y));
    hi = *(unsigned*)&h;
    lo = *(unsigned*)&l;
}

// mma.sync m16n8k16 bf16 -> f32 accumulate
__device__ __forceinline__ void mma16816(float* c, const unsigned* a, const unsigned* b) {
    asm volatile(
        "mma.sync.aligned.m16n8k16.row.col.f32.bf16.bf16.f32 "
        "{%0,%1,%2,%3}, {%4,%5,%6,%7}, {%8,%9}, {%0,%1,%2,%3};"
        : "+f"(c[0]), "+f"(c[1]), "+f"(c[2]), "+f"(c[3])
        : "r"(a[0]), "r"(a[1]), "r"(a[2]), "r"(a[3]), "r"(b[0]), "r"(b[1]));
}

// ldmatrix x4: full 16x16 bf16 A-fragment in one instruction.
__device__ __forceinline__ void ldmat4(unsigned* r, unsigned addr) {
    asm volatile(
        "ldmatrix.sync.aligned.m8n8.x4.shared.b16 {%0,%1,%2,%3}, [%4];"
        : "=r"(r[0]), "=r"(r[1]), "=r"(r[2]), "=r"(r[3]) : "r"(addr));
}

// vector bf16x2 reduction: 8 bf16 dims per 16B RED (halves atomic op count)
__device__ __forceinline__ void red_bf16x8(__nv_bfloat16* p, uint4 v) {
    asm volatile(
        "red.global.add.noftz.v4.bf16x2 [%0], {%1,%2,%3,%4};"
        :: "l"(p), "r"(v.x), "r"(v.y), "r"(v.z), "r"(v.w) : "memory");
}

// ---------------- init: zero pooled sums ------------------------------------
__global__ void k_init() {
    int i = blockIdx.x * 256 + threadIdx.x;
    if (i < NG * D) g_pooled[i] = 0.f;
}

// ---------------- m = h @ W[layer] via bf16x3 tensor cores; zeroes agg ------
__global__ __launch_bounds__(256, 1)
void k_mgemm(const float* __restrict__ x, const float* __restrict__ W, int layer) {
    __shared__ __align__(16) __nv_bfloat16 s_hhi[2][16 * 72];
    __shared__ __align__(16) __nv_bfloat16 s_hlo[2][16 * 72];

    int tid = threadIdx.x;
    int wid = tid >> 5, lane = tid & 31;
    int tg = lane & 3, gid = lane >> 2;
    int dbase = wid * 8;
    int d0 = dbase + tg * 2;

    const float* Wl = W + layer * 64 * 64;
    unsigned Bhi[4][2], Blo[4][2];
#pragma unroll
    for (int kt = 0; kt < 4; kt++) {
        int k0 = kt * 16 + tg * 2;
        int nc = dbase + gid;
        split_pair(Wl[(k0)     * 64 + nc], Wl[(k0 + 1) * 64 + nc], Bhi[kt][0], Blo[kt][0]);
        split_pair(Wl[(k0 + 8) * 64 + nc], Wl[(k0 + 9) * 64 + nc], Bhi[kt][1], Blo[kt][1]);
    }

    const float* hin = layer ? g_h : x;
    int srow = tid >> 4;
    int scol = (tid & 15) * 4;
    const int stride = gridDim.x * 16;

    int chunk = blockIdx.x * 16;
    float4 vh;
    if (chunk < NN) {
        vh = *(const float4*)&hin[chunk * 64 + srow * 64 + scol];
        unsigned h01, l01, h23, l23;
        split2v(make_float2(vh.x, vh.y), h01, l01);
        split2v(make_float2(vh.z, vh.w), h23, l23);
        *(uint2*)&s_hhi[0][srow * 72 + scol] = make_uint2(h01, h23);
        *(uint2*)&s_hlo[0][srow * 72 + scol] = make_uint2(l01, l23);
    }
    __syncthreads();

    for (int it = 0; chunk < NN; chunk += stride, it++) {
        int buf = it & 1;
        int next = chunk + stride;
        if (next < NN)
            vh = *(const float4*)&hin[next * 64 + srow * 64 + scol];

        float C[4] = {0.f, 0.f, 0.f, 0.f};
#pragma unroll
        for (int kt = 0; kt < 4; kt++) {
            int k0 = kt * 16 + tg * 2;
            unsigned ahi[4], alo[4];
            ahi[0] = *(const unsigned*)&s_hhi[buf][(gid)     * 72 + k0];
            ahi[1] = *(const unsigned*)&s_hhi[buf][(gid + 8) * 72 + k0];
            ahi[2] = *(const unsigned*)&s_hhi[buf][(gid)     * 72 + k0 + 8];
            ahi[3] = *(const unsigned*)&s_hhi[buf][(gid + 8) * 72 + k0 + 8];
            alo[0] = *(const unsigned*)&s_hlo[buf][(gid)     * 72 + k0];
            alo[1] = *(const unsigned*)&s_hlo[buf][(gid + 8) * 72 + k0];
            alo[2] = *(const unsigned*)&s_hlo[buf][(gid)     * 72 + k0 + 8];
            alo[3] = *(const unsigned*)&s_hlo[buf][(gid + 8) * 72 + k0 + 8];
            mma16816(C, ahi, Bhi[kt]);
            mma16816(C, ahi, Blo[kt]);
            mma16816(C, alo, Bhi[kt]);
        }

#pragma unroll
        for (int p = 0; p < 2; p++) {
            int node = chunk + gid + p * 8;
            __nv_bfloat162 mv = __float22bfloat162_rn(make_float2(C[p * 2], C[p * 2 + 1]));
            *(__nv_bfloat162*)&g_m[node * 64 + d0] = mv;
            *(unsigned*)&g_agg[node * 64 + d0] = 0u;
        }

        if (next < NN) {
            unsigned h01, l01, h23, l23;
            split2v(make_float2(vh.x, vh.y), h01, l01);
            split2v(make_float2(vh.z, vh.w), h23, l23);
            *(uint2*)&s_hhi[buf ^ 1][srow * 72 + scol] = make_uint2(h01, h23);
            *(uint2*)&s_hlo[buf ^ 1][srow * 72 + scol] = make_uint2(l01, l23);
        }
        __syncthreads();
    }
}

// ---------------- edge scatter: agg[dst] += m[src], all bf16 ----------------
// One thread per (4-edge group, 8-dim chunk): int4 index loads amortized 4x;
// 4 independent 16B bf16 gathers + 4 vector bf16x2 REDs (8 dims per RED ->
// half the atomic-op count of the f32 version).
__global__ void k_scatter(const int* __restrict__ ei) {
    int t = blockIdx.x * 256 + threadIdx.x;
    if (t >= NE * 2) return;
    int c = (t & 7) * 8;   // dim chunk: 8 bf16 dims = 16B
    int eg = t >> 3;       // group of 4 consecutive edges
    int4 s4 = __ldg((const int4*)ei + eg);
    int4 d4 = __ldg((const int4*)(ei + NE) + eg);
    uint4 v0 = *(const uint4*)&g_m[s4.x * 64 + c];
    uint4 v1 = *(const uint4*)&g_m[s4.y * 64 + c];
    uint4 v2 = *(const uint4*)&g_m[s4.z * 64 + c];
    uint4 v3 = *(const uint4*)&g_m[s4.w * 64 + c];
    red_bf16x8(&g_agg[d4.x * 64 + c], v0);
    red_bf16x8(&g_agg[d4.y * 64 + c], v1);
    red_bf16x8(&g_agg[d4.z * 64 + c], v2);
    red_bf16x8(&g_agg[d4.w * 64 + c], v3);
}

// ---------------- fused GRU gates, 16-warp split, 32-node M-tile ------------
// agg is bf16 exactly -> agg-side warps (side 0) need no lo-residual: they
// run 2 MMAs per fragment (hi x Bhi, hi x Blo) instead of 3, and s_alo is gone.
#define MT 32
#define GATES_SMEM ((3 * (2 * MT * 72)) * 2 + 2 * MT * 68 * 4 + 6 * MT * 72 * 4)

__global__ __launch_bounds__(512, 1)
void k_gates(const float* __restrict__ x,
             const float* __restrict__ w_ih, const float* __restrict__ w_hh,
             const float* __restrict__ b_ih, const float* __restrict__ b_hh,
             const int* __restrict__ batch, int layer) {
    extern __shared__ __align__(16) char smraw[];
    __nv_bfloat16* s_ahi = (__nv_bfloat16*)smraw;      // [2][MT*72] (agg, exact bf16)
    __nv_bfloat16* s_hhi = s_ahi + 2 * MT * 72;
    __nv_bfloat16* s_hlo = s_hhi + 2 * MT * 72;
    float* s_hf = (float*)(s_hlo + 2 * MT * 72);       // [2][MT*68]
    float* sC   = s_hf + 2 * MT * 68;                  // [6][MT*72]

    int tid = threadIdx.x;
    int wid = tid >> 5, lane = tid & 31;
    int side = wid >> 3, w8 = wid & 7;
    int tg = lane & 3, gid = lane >> 2;
    int d0 = w8 * 8 + tg * 2;

    const float* wm = side ? w_hh : w_ih;
    unsigned Bhi[3][4][2], Blo[3][4][2];
#pragma unroll
    for (int g = 0; g < 3; g++) {
        const float* wr = wm + (g * 64 + w8 * 8 + gid) * 64;
#pragma unroll
        for (int kt = 0; kt < 4; kt++) {
            int k0 = kt * 16 + tg * 2;
            split_pair(wr[k0],     wr[k0 + 1], Bhi[g][kt][0], Blo[g][kt][0]);
            split_pair(wr[k0 + 8], wr[k0 + 9], Bhi[g][kt][1], Blo[g][kt][1]);
        }
    }

    int srow = tid >> 4;          // 0..31
    int scol = (tid & 15) * 4;
    int erow = tid >> 5;          // 0..15
    int ecol = lane * 2;
    float2 ebi0 = *(const float2*)&b_ih[ecol];
    float2 ebi1 = *(const float2*)&b_ih[64 + ecol];
    float2 ebi2 = *(const float2*)&b_ih[128 + ecol];
    float2 ebh0 = *(const float2*)&b_hh[ecol];
    float2 ebh1 = *(const float2*)&b_hh[64 + ecol];
    float2 ebh2 = *(const float2*)&b_hh[128 + ecol];

    const float* hin = layer ? g_h : x;
    const int stride = gridDim.x * MT;

    unsigned lrow = (lane & 7) + ((lane >> 3) & 1) * 8;  // 0..15
    unsigned lcol = (lane >> 4) * 8;                     // 0 or 8
    unsigned base_hi = (unsigned)__cvta_generic_to_shared(side ? s_hhi : s_ahi);
    unsigned base_lo = (unsigned)__cvta_generic_to_shared(s_hlo);

    int chunk = blockIdx.x * MT;
    uint2 va;
    float4 vh;
    if (chunk + srow < NN) {
        va = *(const uint2*)&g_agg[(chunk + srow) * 64 + scol];
        vh = *(const float4*)&hin[(chunk + srow) * 64 + scol];
        *(uint2*)&s_ahi[srow * 72 + scol] = va;
        unsigned h01, l01, h23, l23;
        split2v(make_float2(vh.x, vh.y), h01, l01);
        split2v(make_float2(vh.z, vh.w), h23, l23);
        *(uint2*)&s_hhi[srow * 72 + scol] = make_uint2(h01, h23);
        *(uint2*)&s_hlo[srow * 72 + scol] = make_uint2(l01, l23);
        *(float4*)&s_hf[srow * 68 + scol] = vh;
    }
    __syncthreads();

    for (int it = 0; chunk < NN; chunk += stride, it++) {
        int buf = it & 1;
        int abase = buf * MT * 72;
        int next = chunk + stride;
        if (next + srow < NN) {
            va = *(const uint2*)&g_agg[(next + srow) * 64 + scol];
            vh = *(const float4*)&hin[(next + srow) * 64 + scol];
        }

        float C[3][2][4];
#pragma unroll
        for (int g = 0; g < 3; g++)
#pragma unroll
            for (int rb = 0; rb < 2; rb++)
#pragma unroll
                for (int q = 0; q < 4; q++) C[g][rb][q] = 0.f;

        if (side == 0) {
            // agg side: exact bf16 A -> 2 MMAs per fragment
#pragma unroll
            for (int kt = 0; kt < 4; kt++) {
#pragma unroll
                for (int rb = 0; rb < 2; rb++) {
                    unsigned off = (unsigned)((abase + (rb * 16 + lrow) * 72 +
                                               kt * 16 + lcol) * 2);
                    unsigned ahi[4];
                    ldmat4(ahi, base_hi + off);
#pragma unroll
                    for (int g = 0; g < 3; g++) {
                        mma16816(C[g][rb], ahi, Bhi[g][kt]);
                        mma16816(C[g][rb], ahi, Blo[g][kt]);
                    }
                }
            }
        } else {
            // h side: bf16x3 (hi/lo split)
#pragma unroll
            for (int kt = 0; kt < 4; kt++) {
#pragma unroll
                for (int rb = 0; rb < 2; rb++) {
                    unsigned off = (unsigned)((abase + (rb * 16 + lrow) * 72 +
                                               kt * 16 + lcol) * 2);
                    unsigned ahi[4], alo[4];
                    ldmat4(ahi, base_hi + off);
                    ldmat4(alo, base_lo + off);
#pragma unroll
                    for (int g = 0; g < 3; g++) {
                        mma16816(C[g][rb], ahi, Bhi[g][kt]);
                        mma16816(C[g][rb], ahi, Blo[g][kt]);
                        mma16816(C[g][rb], alo, Bhi[g][kt]);
                    }
                }
            }
        }

#pragma unroll
        for (int g = 0; g < 3; g++)
#pragma unroll
            for (int rb = 0; rb < 2; rb++)
#pragma unroll
                for (int p = 0; p < 2; p++)
                    *(float2*)&sC[((side * 3 + g) * MT + rb * 16 + gid + p * 8) * 72 + d0] =
                        make_float2(C[g][rb][2 * p], C[g][rb][2 * p + 1]);
        __syncthreads();

#pragma unroll
        for (int rr = 0; rr < 2; rr++) {
            int row = erow + rr * 16;
            int node = chunk + row;
            if (node < NN) {
                float2 ir = *(float2*)&sC[(0 * MT + row) * 72 + ecol];
                float2 iz = *(float2*)&sC[(1 * MT + row) * 72 + ecol];
                float2 ix = *(float2*)&sC[(2 * MT + row) * 72 + ecol];
                float2 hr = *(float2*)&sC[(3 * MT + row) * 72 + ecol];
                float2 hz = *(float2*)&sC[(4 * MT + row) * 72 + ecol];
                float2 hn = *(float2*)&sC[(5 * MT + row) * 72 + ecol];
                float2 ho = *(float2*)&s_hf[buf * MT * 68 + row * 68 + ecol];

                float r0 = sigf(ir.x + ebi0.x + hr.x + ebh0.x);
                float z0 = sigf(iz.x + ebi1.x + hz.x + ebh1.x);
                float n0 = tanhfast(ix.x + ebi2.x + r0 * (hn.x + ebh2.x));
                float h0 = (1.f - z0) * n0 + z0 * ho.x;
                float r1 = sigf(ir.y + ebi0.y + hr.y + ebh0.y);
                float z1 = sigf(iz.y + ebi1.y + hz.y + ebh1.y);
                float n1 = tanhfast(ix.y + ebi2.y + r1 * (hn.y + ebh2.y));
                float h1 = (1.f - z1) * n1 + z1 * ho.y;

                if (layer == 0) {
                    *(float2*)&g_h[node * 64 + ecol] = make_float2(h0, h1);
                } else {
                    float2 rv = make_float2(fmaxf(h0, 0.f), fmaxf(h1, 0.f));
                    atomicAdd((float2*)&g_pooled[batch[node] * 64 + ecol], rv);
                }
            }
        }

        if (next + srow < NN) {
            *(uint2*)&s_ahi[(buf ^ 1) * MT * 72 + srow * 72 + scol] = va;
            unsigned h01, l01, h23, l23;
            split2v(make_float2(vh.x, vh.y), h01, l01);
            split2v(make_float2(vh.z, vh.w), h23, l23);
            *(uint2*)&s_hhi[(buf ^ 1) * MT * 72 + srow * 72 + scol] = make_uint2(h01, h23);
            *(uint2*)&s_hlo[(buf ^ 1) * MT * 72 + srow * 72 + scol] = make_uint2(l01, l23);
            *(float4*)&s_hf[(buf ^ 1) * MT * 68 + srow * 68 + scol] = vh;
        }
        __syncthreads();
    }
}

// ---------------- mean pool + fc1(relu) + fc2 + log_softmax -----------------
__device__ __forceinline__ int lbound(const int* __restrict__ b, int v) {
    int lo = 0, hi = NN;
    while (lo < hi) {
        int m = (lo + hi) >> 1;
        if (b[m] < v) lo = m + 1; else hi = m;
    }
    return lo;
}

__global__ void k_poolfc(const int* __restrict__ batch,
                         const float* __restrict__ fc1w, const float* __restrict__ fc1b,
                         const float* __restrict__ fc2w, const float* __restrict__ fc2b,
                         float* __restrict__ out) {
    int g = threadIdx.x;
    if (g >= NG) return;
    int cnt = lbound(batch, g + 1) - lbound(batch, g);
    float inv = 1.f / fmaxf((float)cnt, 1.f);
    float p[D];
#pragma unroll
    for (int k = 0; k < D; k++) p[k] = g_pooled[g * D + k] * inv;

    float y[DH];
#pragma unroll
    for (int j = 0; j < DH; j++) {
        float s = fc1b[j];
#pragma unroll
        for (int k = 0; k < D; k++) s += p[k] * fc1w[j * D + k];
        y[j] = fmaxf(s, 0.f);
    }

    float z[NC];
    float mx = -1e30f;
#pragma unroll
    for (int c = 0; c < NC; c++) {
        float s = fc2b[c];
#pragma unroll
        for (int j = 0; j < DH; j++) s += y[j] * fc2w[c * DH + j];
        z[c] = s;
        mx = fmaxf(mx, s);
    }
    float lse = 0.f;
#pragma unroll
    for (int c = 0; c < NC; c++) lse += expf(z[c] - mx);
    lse = logf(lse) + mx;
#pragma unroll
    for (int c = 0; c < NC; c++) out[g * NC + c] = z[c] - lse;
}

// ---------------- launch -----------------------------------------------------
extern "C" void kernel_launch(void* const* d_in, const int* in_sizes, int n_in,
                              void* d_out, int out_size) {
    const float* x     = (const float*)d_in[0];
    const int*   ei    = (const int*)d_in[1];
    const int*   batch = (const int*)d_in[2];
    const float* W     = (const float*)d_in[3];
    const float* w_ih  = (const float*)d_in[4];
    const float* w_hh  = (const float*)d_in[5];
    const float* b_ih  = (const float*)d_in[6];
    const float* b_hh  = (const float*)d_in[7];
    const float* fc1w  = (const float*)d_in[8];
    const float* fc1b  = (const float*)d_in[9];
    const float* fc2w  = (const float*)d_in[10];
    const float* fc2b  = (const float*)d_in[11];
    float* out = (float*)d_out;

    cudaFuncSetAttribute(k_gates, cudaFuncAttributeMaxDynamicSharedMemorySize,
                         GATES_SMEM);

    k_init<<<32, 256>>>();

    for (int l = 0; l < 2; l++) {
        k_mgemm<<<592, 256>>>(x, W, l);
        k_scatter<<<(NE * 2 + 255) / 256, 256>>>(ei);
        k_gates<<<148, 512, GATES_SMEM>>>(x, w_ih, w_hh, b_ih, b_hh, batch, l);
    }
    k_poolfc<<<1, 128>>>(batch, fc1w, fc1b, fc2w, fc2b, out);
}